// round 13
// baseline (speedup 1.0000x reference)
#include <cuda_runtime.h>
#include <cstdint>

#define G_   200
#define NPG  500
#define EPG  6000
#define ETOT (G_*EPG)
#define F_   64
#define KPG  250
#define NTH  512
#define NW   (NTH/32)

struct __align__(16) SmemLayout {
    float           arena[NPG * 32];            // u64 sort buf(P2) / HB(P3+)
    union {                                     // 24832B
        struct {
            float W1s[F_][F_];                  // 16384B (P3+)
            float b1s[F_];
            float zst[NW][2][F_];               // 8192B
        } mm;
        unsigned pe[EPG];                       // packed (r<<16|c) edges (P0)
    } u2;
    unsigned short  csr_src[EPG];               // 12000B; overlaid by rsum/rmax at readout
    unsigned        col_off[NPG + 4];
    float           dis[NPG];
    float           scorev[NTH];                // icnt(P0) -> scores(P1) -> logit_s(P3b+)
    int             sidx[NTH];                  // outdeg(P0)
    int             wsum[32];
    unsigned short  klist[KPG + 2];
    short           mapv[NPG];
    float           d2k[KPG];
    float           ninv[KPG];
    unsigned short  vcnt[KPG + 2];
};

__device__ __forceinline__ float warp_sum(float v) {
    #pragma unroll
    for (int o = 16; o; o >>= 1) v += __shfl_xor_sync(0xffffffffu, v, o);
    return v;
}
__device__ __forceinline__ unsigned long long shfl_xor_u64(unsigned long long v, int m) {
    unsigned lo = (unsigned)v, hi = (unsigned)(v >> 32);
    lo = __shfl_xor_sync(0xffffffffu, lo, m);
    hi = __shfl_xor_sync(0xffffffffu, hi, m);
    return ((unsigned long long)hi << 32) | lo;
}

__global__ __launch_bounds__(NTH, 2)
void gp_fused_kernel(const float* __restrict__ x,
                     const int*   __restrict__ ei,
                     const float* __restrict__ W1,
                     const float* __restrict__ b1,
                     const float* __restrict__ beta_p,
                     float*       __restrict__ out)
{
    extern __shared__ __align__(16) unsigned char smraw[];
    SmemLayout& S = *reinterpret_cast<SmemLayout*>(smraw);

    const int g    = blockIdx.x;
    const int tid  = threadIdx.x;
    const int wid  = tid >> 5;
    const int lane = tid & 31;
    const int base = g * NPG;
    const int* __restrict__ erow = ei + (size_t)g * EPG;
    const int* __restrict__ ecol = ei + (size_t)ETOT + (size_t)g * EPG;
    const float* __restrict__ xg = x + (size_t)base * F_;

    // ===== Phase 0: degrees + packed-edge cache + CSR ========================
    int* icnt = reinterpret_cast<int*>(S.scorev);
    icnt[tid]   = 0;
    S.sidx[tid] = 0;
    __syncthreads();

    for (int e = tid; e < EPG; e += NTH) {          // single global edge sweep
        int r = erow[e] - base;
        int c = ecol[e] - base;
        S.u2.pe[e] = ((unsigned)r << 16) | (unsigned)c;
        atomicAdd(&S.sidx[r], 1);
        atomicAdd(&icnt[c],  1);
    }
    __syncthreads();

    for (int n = tid; n < NPG; n += NTH) {
        int d = S.sidx[n];
        S.dis[n] = (d > 0) ? (1.0f / sqrtf((float)d)) : 0.0f;
    }
    {   // hierarchical exclusive scan of icnt -> col_off starts
        int v = icnt[tid];
        int inc = v;
        #pragma unroll
        for (int o = 1; o < 32; o <<= 1) {
            int u = __shfl_up_sync(0xffffffffu, inc, o);
            if (lane >= o) inc += u;
        }
        if (lane == 31) S.wsum[wid] = inc;
        __syncthreads();
        if (tid < 16) {
            int s = S.wsum[tid];
            #pragma unroll
            for (int o = 1; o < 16; o <<= 1) {
                int u = __shfl_up_sync(0x0000ffffu, s, o);
                if (tid >= o) s += u;
            }
            S.wsum[tid] = s;
        }
        __syncthreads();
        int pre = (wid > 0) ? S.wsum[wid - 1] : 0;
        if (tid < NPG + 1) S.col_off[tid] = (unsigned)(inc - v + pre);
    }
    __syncthreads();

    for (int e = tid; e < EPG; e += NTH) {          // scatter from SMEM cache
        unsigned p = S.u2.pe[e];
        int r = (int)(p >> 16);
        int c = (int)(p & 0xffffu);
        unsigned pos = atomicAdd(&S.col_off[c], 1u);
        S.csr_src[pos] = (unsigned short)r;
    }
    __syncthreads();
    // segment(n) = [ n? col_off[n-1]:0 , col_off[n] )

    // ===== Phase 1: score, single pass from global, ILP-8 ===================
    for (int n = wid; n < NPG; n += NW) {
        const float2* xr = reinterpret_cast<const float2*>(xg + (size_t)n * F_);
        float2 xc = xr[lane];
        float  dn = S.dis[n];
        unsigned kb = n ? S.col_off[n - 1] : 0u;
        unsigned ke = S.col_off[n];
        float2 a0 = make_float2(0.f, 0.f), a1 = make_float2(0.f, 0.f);
        float2 a2 = make_float2(0.f, 0.f), a3 = make_float2(0.f, 0.f);
        unsigned k = kb;
        for (; k + 8 <= ke; k += 8) {
            int s0 = S.csr_src[k + 0], s1 = S.csr_src[k + 1];
            int s2 = S.csr_src[k + 2], s3 = S.csr_src[k + 3];
            int s4 = S.csr_src[k + 4], s5 = S.csr_src[k + 5];
            int s6 = S.csr_src[k + 6], s7 = S.csr_src[k + 7];
            float2 v0 = reinterpret_cast<const float2*>(xg + (size_t)s0 * F_)[lane];
            float2 v1 = reinterpret_cast<const float2*>(xg + (size_t)s1 * F_)[lane];
            float2 v2 = reinterpret_cast<const float2*>(xg + (size_t)s2 * F_)[lane];
            float2 v3 = reinterpret_cast<const float2*>(xg + (size_t)s3 * F_)[lane];
            float2 v4 = reinterpret_cast<const float2*>(xg + (size_t)s4 * F_)[lane];
            float2 v5 = reinterpret_cast<const float2*>(xg + (size_t)s5 * F_)[lane];
            float2 v6 = reinterpret_cast<const float2*>(xg + (size_t)s6 * F_)[lane];
            float2 v7 = reinterpret_cast<const float2*>(xg + (size_t)s7 * F_)[lane];
            float w0 = S.dis[s0] * dn, w1 = S.dis[s1] * dn;
            float w2 = S.dis[s2] * dn, w3 = S.dis[s3] * dn;
            float w4 = S.dis[s4] * dn, w5 = S.dis[s5] * dn;
            float w6 = S.dis[s6] * dn, w7 = S.dis[s7] * dn;
            a0.x = fmaf(w0, v0.x, a0.x);  a0.y = fmaf(w0, v0.y, a0.y);
            a1.x = fmaf(w1, v1.x, a1.x);  a1.y = fmaf(w1, v1.y, a1.y);
            a2.x = fmaf(w2, v2.x, a2.x);  a2.y = fmaf(w2, v2.y, a2.y);
            a3.x = fmaf(w3, v3.x, a3.x);  a3.y = fmaf(w3, v3.y, a3.y);
            a0.x = fmaf(w4, v4.x, a0.x);  a0.y = fmaf(w4, v4.y, a0.y);
            a1.x = fmaf(w5, v5.x, a1.x);  a1.y = fmaf(w5, v5.y, a1.y);
            a2.x = fmaf(w6, v6.x, a2.x);  a2.y = fmaf(w6, v6.y, a2.y);
            a3.x = fmaf(w7, v7.x, a3.x);  a3.y = fmaf(w7, v7.y, a3.y);
        }
        for (; k + 2 <= ke; k += 2) {
            int s0 = S.csr_src[k + 0], s1 = S.csr_src[k + 1];
            float2 v0 = reinterpret_cast<const float2*>(xg + (size_t)s0 * F_)[lane];
            float2 v1 = reinterpret_cast<const float2*>(xg + (size_t)s1 * F_)[lane];
            float w0 = S.dis[s0] * dn, w1 = S.dis[s1] * dn;
            a0.x = fmaf(w0, v0.x, a0.x);  a0.y = fmaf(w0, v0.y, a0.y);
            a1.x = fmaf(w1, v1.x, a1.x);  a1.y = fmaf(w1, v1.y, a1.y);
        }
        for (; k < ke; ++k) {
            int s = S.csr_src[k];
            float2 v0 = reinterpret_cast<const float2*>(xg + (size_t)s * F_)[lane];
            float w = S.dis[s] * dn;
            a0.x = fmaf(w, v0.x, a0.x);  a0.y = fmaf(w, v0.y, a0.y);
        }
        float ax = (a0.x + a1.x) + (a2.x + a3.x);
        float ay = (a0.y + a1.y) + (a2.y + a3.y);
        float v = warp_sum(fabsf(xc.x - ax) + fabsf(xc.y - ay));
        if (lane == 0) S.scorev[n] = v;
    }
    if (tid >= NPG) S.scorev[tid] = -3.4e38f;
    __syncthreads();

    // ====== Phase 2: hybrid bitonic sort on packed u64 (score desc, idx asc)
    unsigned long long key;
    {
        float sc = S.scorev[tid];
        unsigned sb  = __float_as_uint(sc);
        unsigned ord = (sb & 0x80000000u) ? ~sb : (sb | 0x80000000u);
        key = ((unsigned long long)ord << 32) | (unsigned)(~tid);
    }
    unsigned long long* kb64 = reinterpret_cast<unsigned long long*>(S.arena);

    #pragma unroll
    for (int k = 2; k <= 32; k <<= 1) {         // k = 2..32 in registers
        #pragma unroll
        for (int j = k >> 1; j > 0; j >>= 1) {
            unsigned long long pk = shfl_xor_u64(key, j);
            bool isLow   = ((lane & j) == 0);
            bool dirDesc = ((tid  & k) == 0);
            bool takeMax = (isLow == dirDesc);
            key = ((pk > key) == takeMax) ? pk : key;
        }
    }
    #pragma unroll
    for (int k = 64; k <= NTH; k <<= 1) {       // k = 64..512
        for (int j = k >> 1; j >= 32; j >>= 1) {
            kb64[tid] = key;
            __syncthreads();
            unsigned long long pk = kb64[tid ^ j];
            bool isLow   = ((tid & j) == 0);
            bool dirDesc = ((tid & k) == 0);
            bool takeMax = (isLow == dirDesc);
            key = ((pk > key) == takeMax) ? pk : key;
            __syncthreads();
        }
        #pragma unroll
        for (int j = 16; j > 0; j >>= 1) {
            unsigned long long pk = shfl_xor_u64(key, j);
            bool isLow   = ((lane & j) == 0);
            bool dirDesc = ((tid  & k) == 0);
            bool takeMax = (isLow == dirDesc);
            key = ((pk > key) == takeMax) ? pk : key;
        }
    }
    for (int n = tid; n < NPG; n += NTH) S.mapv[n] = -1;
    __syncthreads();
    if (tid < KPG) {
        int idx = (int)(~(unsigned)key) & (NTH - 1);
        S.klist[tid] = (unsigned short)idx;
        S.mapv[idx]  = (short)tid;
    }
    __syncthreads();

    // ====== Phase 3a: W1/b1 stage, in-place CSR compaction, d2 ==============
    {
        const float4* src = reinterpret_cast<const float4*>(W1);
        float4*       dst = reinterpret_cast<float4*>(&S.u2.mm.W1s[0][0]);
        for (int i = tid; i < F_ * F_ / 4; i += NTH) dst[i] = src[i];
    }
    if (tid < F_) S.u2.mm.b1s[tid] = b1[tid];
    const float beta = beta_p[0];

    if (tid < KPG) {
        int n = S.klist[tid];
        unsigned kb = n ? S.col_off[n - 1] : 0u;
        unsigned ke = S.col_off[n];
        unsigned w  = kb;
        for (unsigned k = kb; k < ke; ++k) {
            short m = S.mapv[S.csr_src[k]];
            if (m >= 0) S.csr_src[w++] = (unsigned short)m;
        }
        int cnt = (int)(w - kb);
        S.vcnt[tid] = (unsigned short)cnt;
        S.d2k[tid]  = 1.0f / sqrtf((float)(cnt + 1));
    }
    __syncthreads();

    // ====== Phase 3b: interleaved 2-row z-gather + matmul + fused 4a ========
    float2* HB2 = reinterpret_cast<float2*>(S.arena);
    const float2* W2 = reinterpret_cast<const float2*>(&S.u2.mm.W1s[0][0]);
    {
        float2 b2 = reinterpret_cast<const float2*>(S.u2.mm.b1s)[lane];
        for (int i0 = 2 * wid; i0 < KPG; i0 += 2 * NW) {
            const int iA = i0;
            const bool hasB = (i0 + 1 < KPG);
            const int iB = hasB ? i0 + 1 : i0;
            int nA = S.klist[iA], nB = S.klist[iB];
            float dA = S.d2k[iA], dB = S.d2k[iB];
            float2 xvA = reinterpret_cast<const float2*>(xg + (size_t)nA * F_)[lane];
            float2 xvB = reinterpret_cast<const float2*>(xg + (size_t)nB * F_)[lane];
            float2 zA = make_float2(dA * dA * xvA.x, dA * dA * xvA.y);
            float2 zB = make_float2(dB * dB * xvB.x, dB * dB * xvB.y);
            unsigned kbA = nA ? S.col_off[nA - 1] : 0u;
            unsigned kbB = nB ? S.col_off[nB - 1] : 0u;
            int cntA = (int)S.vcnt[iA];
            int cntB = hasB ? (int)S.vcnt[iB] : 0;
            int kmax = cntA > cntB ? cntA : cntB;
            for (int k = 0; k < kmax; ++k) {
                if (k < cntA) {
                    int rs = S.csr_src[kbA + k];
                    float nm = S.d2k[rs] * dA;
                    float2 xw = reinterpret_cast<const float2*>(
                        xg + (size_t)S.klist[rs] * F_)[lane];
                    zA.x = fmaf(nm, xw.x, zA.x);
                    zA.y = fmaf(nm, xw.y, zA.y);
                }
                if (k < cntB) {
                    int rs = S.csr_src[kbB + k];
                    float nm = S.d2k[rs] * dB;
                    float2 xw = reinterpret_cast<const float2*>(
                        xg + (size_t)S.klist[rs] * F_)[lane];
                    zB.x = fmaf(nm, xw.x, zB.x);
                    zB.y = fmaf(nm, xw.y, zB.y);
                }
            }
            reinterpret_cast<float2*>(S.u2.mm.zst[wid][0])[lane] = zA;
            reinterpret_cast<float2*>(S.u2.mm.zst[wid][1])[lane] = zB;
            __syncwarp();
            float2 a0 = b2, a1 = b2;
            #pragma unroll
            for (int k2 = 0; k2 < F_; ++k2) {
                float2 w = W2[k2 * 32 + lane];
                float z0 = S.u2.mm.zst[wid][0][k2];
                float z1 = S.u2.mm.zst[wid][1][k2];
                a0.x = fmaf(z0, w.x, a0.x);  a0.y = fmaf(z0, w.y, a0.y);
                a1.x = fmaf(z1, w.x, a1.x);  a1.y = fmaf(z1, w.y, a1.y);
            }
            a0.x = fmaxf(a0.x, 0.f);  a0.y = fmaxf(a0.y, 0.f);
            a1.x = fmaxf(a1.x, 0.f);  a1.y = fmaxf(a1.y, 0.f);
            HB2[iA * 32 + lane] = a0;
            {
                float ss = warp_sum(a0.x * a0.x + a0.y * a0.y);
                float ni = 1.0f / fmaxf(sqrtf(ss), 1e-12f);
                if (lane == 0) {
                    S.ninv[iA]   = ni;
                    S.scorev[iA] = beta * ss * ni * ni;
                }
            }
            if (hasB) {
                HB2[iB * 32 + lane] = a1;
                float ss = warp_sum(a1.x * a1.x + a1.y * a1.y);
                float ni = 1.0f / fmaxf(sqrtf(ss), 1e-12f);
                if (lane == 0) {
                    S.ninv[iB]   = ni;
                    S.scorev[iB] = beta * ss * ni * ni;
                }
            }
            __syncwarp();
        }
    }
    __syncthreads();

    // ====== Phase 4: AGNN chunk-4 online softmax + fused readout ============
    float2 msum = make_float2(0.f, 0.f);
    float2 mmax = make_float2(-3.4e38f, -3.4e38f);
    for (int i = wid; i < KPG; i += NW) {
        int n = S.klist[i];
        unsigned kb = n ? S.col_off[n - 1] : 0u;
        int dv = (int)S.vcnt[i];
        float ni = S.ninv[i];
        float2 hn = HB2[i * 32 + lane];
        float m     = S.scorev[i];                  // logit_s
        float denom = 1.0f;
        float2 acc  = hn;
        for (int c = 0; c < dv; c += 4) {
            int cnt = dv - c;  if (cnt > 4) cnt = 4;
            int   rs0, rs1, rs2, rs3;
            float d0, d1, d2, d3;
            rs0 = S.csr_src[kb + c];
            rs1 = (cnt > 1) ? (int)S.csr_src[kb + c + 1] : rs0;
            rs2 = (cnt > 2) ? (int)S.csr_src[kb + c + 2] : rs0;
            rs3 = (cnt > 3) ? (int)S.csr_src[kb + c + 3] : rs0;
            {
                float2 h0 = HB2[rs0 * 32 + lane];
                float2 h1 = HB2[rs1 * 32 + lane];
                float2 h2 = HB2[rs2 * 32 + lane];
                float2 h3 = HB2[rs3 * 32 + lane];
                d0 = fmaf(hn.x, h0.x, hn.y * h0.y);
                d1 = fmaf(hn.x, h1.x, hn.y * h1.y);
                d2 = fmaf(hn.x, h2.x, hn.y * h2.y);
                d3 = fmaf(hn.x, h3.x, hn.y * h3.y);
            }
            #pragma unroll
            for (int o = 16; o; o >>= 1) {          // 4 interleaved trees
                d0 += __shfl_xor_sync(0xffffffffu, d0, o);
                d1 += __shfl_xor_sync(0xffffffffu, d1, o);
                d2 += __shfl_xor_sync(0xffffffffu, d2, o);
                d3 += __shfl_xor_sync(0xffffffffu, d3, o);
            }
            d0 = beta * d0 * ni * S.ninv[rs0];
            d1 = (cnt > 1) ? beta * d1 * ni * S.ninv[rs1] : -3.4e38f;
            d2 = (cnt > 2) ? beta * d2 * ni * S.ninv[rs2] : -3.4e38f;
            d3 = (cnt > 3) ? beta * d3 * ni * S.ninv[rs3] : -3.4e38f;
            float cm = fmaxf(fmaxf(d0, d1), fmaxf(d2, d3));
            float mn = fmaxf(m, cm);
            float cr = __expf(m - mn);
            denom *= cr;
            acc.x *= cr;  acc.y *= cr;
            {
                float e0 = __expf(d0 - mn);
                float2 hs = HB2[rs0 * 32 + lane];
                denom += e0;
                acc.x = fmaf(e0, hs.x, acc.x);
                acc.y = fmaf(e0, hs.y, acc.y);
            }
            if (cnt > 1) {
                float e1 = __expf(d1 - mn);
                float2 hs = HB2[rs1 * 32 + lane];
                denom += e1;
                acc.x = fmaf(e1, hs.x, acc.x);
                acc.y = fmaf(e1, hs.y, acc.y);
            }
            if (cnt > 2) {
                float e2 = __expf(d2 - mn);
                float2 hs = HB2[rs2 * 32 + lane];
                denom += e2;
                acc.x = fmaf(e2, hs.x, acc.x);
                acc.y = fmaf(e2, hs.y, acc.y);
            }
            if (cnt > 3) {
                float e3 = __expf(d3 - mn);
                float2 hs = HB2[rs3 * 32 + lane];
                denom += e3;
                acc.x = fmaf(e3, hs.x, acc.x);
                acc.y = fmaf(e3, hs.y, acc.y);
            }
            m = mn;
        }
        float inv = 1.0f / denom;
        float2 o = make_float2(acc.x * inv, acc.y * inv);
        msum.x += o.x;  msum.y += o.y;
        mmax.x = fmaxf(mmax.x, o.x);
        mmax.y = fmaxf(mmax.y, o.y);
    }
    __syncthreads();                                 // csr_src now dead
    {
        float* RS = reinterpret_cast<float*>(S.csr_src);        // [16][64]
        float* RM = RS + NW * F_;                               // [16][64]
        reinterpret_cast<float2*>(RS)[wid * 32 + lane] = msum;
        reinterpret_cast<float2*>(RM)[wid * 32 + lane] = mmax;
        __syncthreads();
        if (tid < F_) {
            float s = 0.f;
            #pragma unroll
            for (int w = 0; w < NW; ++w) s += RS[w * F_ + tid];
            out[(size_t)g * (2 * F_) + tid] = fmaxf(s * (1.0f / (float)KPG), 0.f);
        } else if (tid < 2 * F_) {
            int f = tid - F_;
            float m2 = -3.4e38f;
            #pragma unroll
            for (int w = 0; w < NW; ++w) m2 = fmaxf(m2, RM[w * F_ + f]);
            out[(size_t)g * (2 * F_) + F_ + f] = fmaxf(m2, 0.f);
        }
    }
}

extern "C" void kernel_launch(void* const* d_in, const int* in_sizes, int n_in,
                              void* d_out, int out_size)
{
    const float* x    = (const float*)d_in[0];
    const int*   ei   = (const int*)  d_in[1];
    const float* W1   = (const float*)d_in[2];
    const float* b1   = (const float*)d_in[3];
    const float* beta = (const float*)d_in[4];
    float*       out  = (float*)d_out;

    int smem = (int)sizeof(SmemLayout);
    cudaFuncSetAttribute(gp_fused_kernel,
                         cudaFuncAttributeMaxDynamicSharedMemorySize, smem);
    gp_fused_kernel<<<G_, NTH, smem>>>(x, ei, W1, b1, beta, out);
}

// round 14
// speedup vs baseline: 1.0514x; 1.0514x over previous
#include <cuda_runtime.h>
#include <cstdint>

#define G_   200
#define NPG  500
#define EPG  6000
#define ETOT (G_*EPG)
#define F_   64
#define KPG  250
#define NTH  512
#define NW   (NTH/32)

struct __align__(16) SmemLayout {
    float           arena[NPG * 32];            // u64 sort buf(P2) / HB(P3+)
    union {                                     // 24832B
        struct {
            float W1s[F_][F_];                  // 16384B (P3+)
            float b1s[F_];
            float zst[NW][2][F_];               // 8192B
        } mm;
        unsigned pe[EPG];                       // packed (r<<16|c) edges (P0)
    } u2;
    unsigned short  csr_src[EPG];               // 12000B; overlaid by rsum/rmax at readout
    unsigned        col_off[NPG + 4];
    float           dis[NPG];
    float           scorev[NTH];                // icnt(P0) -> scores(P1) -> logit_s(P3b+)
    int             sidx[NTH];                  // outdeg(P0)
    int             wsum[32];
    unsigned short  klist[KPG + 2];
    short           mapv[NPG];
    float           d2k[KPG];
    float           ninv[KPG];
    unsigned short  vcnt[KPG + 2];
};

__device__ __forceinline__ float warp_sum(float v) {
    #pragma unroll
    for (int o = 16; o; o >>= 1) v += __shfl_xor_sync(0xffffffffu, v, o);
    return v;
}
__device__ __forceinline__ unsigned long long shfl_xor_u64(unsigned long long v, int m) {
    unsigned lo = (unsigned)v, hi = (unsigned)(v >> 32);
    lo = __shfl_xor_sync(0xffffffffu, lo, m);
    hi = __shfl_xor_sync(0xffffffffu, hi, m);
    return ((unsigned long long)hi << 32) | lo;
}

__global__ __launch_bounds__(NTH, 2)
void gp_fused_kernel(const float* __restrict__ x,
                     const int*   __restrict__ ei,
                     const float* __restrict__ W1,
                     const float* __restrict__ b1,
                     const float* __restrict__ beta_p,
                     float*       __restrict__ out)
{
    extern __shared__ __align__(16) unsigned char smraw[];
    SmemLayout& S = *reinterpret_cast<SmemLayout*>(smraw);

    const int g    = blockIdx.x;
    const int tid  = threadIdx.x;
    const int wid  = tid >> 5;
    const int lane = tid & 31;
    const int base = g * NPG;
    const int* __restrict__ erow = ei + (size_t)g * EPG;
    const int* __restrict__ ecol = ei + (size_t)ETOT + (size_t)g * EPG;
    const float* __restrict__ xg = x + (size_t)base * F_;

    // ===== Phase 0: degrees + packed-edge cache + CSR ========================
    int* icnt = reinterpret_cast<int*>(S.scorev);
    icnt[tid]   = 0;
    S.sidx[tid] = 0;
    __syncthreads();

    for (int e = tid; e < EPG; e += NTH) {          // single global edge sweep
        int r = erow[e] - base;
        int c = ecol[e] - base;
        S.u2.pe[e] = ((unsigned)r << 16) | (unsigned)c;
        atomicAdd(&S.sidx[r], 1);
        atomicAdd(&icnt[c],  1);
    }
    __syncthreads();

    for (int n = tid; n < NPG; n += NTH) {
        int d = S.sidx[n];
        S.dis[n] = (d > 0) ? (1.0f / sqrtf((float)d)) : 0.0f;
    }
    {   // hierarchical exclusive scan of icnt -> col_off starts
        int v = icnt[tid];
        int inc = v;
        #pragma unroll
        for (int o = 1; o < 32; o <<= 1) {
            int u = __shfl_up_sync(0xffffffffu, inc, o);
            if (lane >= o) inc += u;
        }
        if (lane == 31) S.wsum[wid] = inc;
        __syncthreads();
        if (tid < 16) {
            int s = S.wsum[tid];
            #pragma unroll
            for (int o = 1; o < 16; o <<= 1) {
                int u = __shfl_up_sync(0x0000ffffu, s, o);
                if (tid >= o) s += u;
            }
            S.wsum[tid] = s;
        }
        __syncthreads();
        int pre = (wid > 0) ? S.wsum[wid - 1] : 0;
        if (tid < NPG + 1) S.col_off[tid] = (unsigned)(inc - v + pre);
    }
    __syncthreads();

    for (int e = tid; e < EPG; e += NTH) {          // scatter from SMEM cache
        unsigned p = S.u2.pe[e];
        int r = (int)(p >> 16);
        int c = (int)(p & 0xffffu);
        unsigned pos = atomicAdd(&S.col_off[c], 1u);
        S.csr_src[pos] = (unsigned short)r;
    }
    __syncthreads();
    // segment(n) = [ n? col_off[n-1]:0 , col_off[n] )

    // ===== Phase 1: score — half-warp float4 edges (2 edges/warp-iter) ======
    {
        const int hw = lane >> 4;                   // half-warp id (0/1)
        const int hl = lane & 15;                   // lane within half
        for (int n = wid; n < NPG; n += NW) {
            float4 xc = reinterpret_cast<const float4*>(xg + (size_t)n * F_)[hl];
            float  dn = S.dis[n];
            unsigned kb = n ? S.col_off[n - 1] : 0u;
            unsigned ke = S.col_off[n];
            float4 a0 = make_float4(0.f, 0.f, 0.f, 0.f);
            float4 a1 = make_float4(0.f, 0.f, 0.f, 0.f);
            unsigned k = kb + (unsigned)hw;
            for (; k + 2 < ke; k += 4) {            // 2 edges for this half
                int s0 = S.csr_src[k];
                int s1 = S.csr_src[k + 2];
                float4 v0 = reinterpret_cast<const float4*>(xg + (size_t)s0 * F_)[hl];
                float4 v1 = reinterpret_cast<const float4*>(xg + (size_t)s1 * F_)[hl];
                float w0 = S.dis[s0] * dn;
                float w1 = S.dis[s1] * dn;
                a0.x = fmaf(w0, v0.x, a0.x);  a0.y = fmaf(w0, v0.y, a0.y);
                a0.z = fmaf(w0, v0.z, a0.z);  a0.w = fmaf(w0, v0.w, a0.w);
                a1.x = fmaf(w1, v1.x, a1.x);  a1.y = fmaf(w1, v1.y, a1.y);
                a1.z = fmaf(w1, v1.z, a1.z);  a1.w = fmaf(w1, v1.w, a1.w);
            }
            for (; k < ke; k += 2) {                // remainder edge
                int s = S.csr_src[k];
                float4 v = reinterpret_cast<const float4*>(xg + (size_t)s * F_)[hl];
                float w = S.dis[s] * dn;
                a0.x = fmaf(w, v.x, a0.x);  a0.y = fmaf(w, v.y, a0.y);
                a0.z = fmaf(w, v.z, a0.z);  a0.w = fmaf(w, v.w, a0.w);
            }
            a0.x += a1.x;  a0.y += a1.y;  a0.z += a1.z;  a0.w += a1.w;
            // combine the two halves (each holds a partial over its edges)
            a0.x += __shfl_xor_sync(0xffffffffu, a0.x, 16);
            a0.y += __shfl_xor_sync(0xffffffffu, a0.y, 16);
            a0.z += __shfl_xor_sync(0xffffffffu, a0.z, 16);
            a0.w += __shfl_xor_sync(0xffffffffu, a0.w, 16);
            float diff = fabsf(xc.x - a0.x) + fabsf(xc.y - a0.y)
                       + fabsf(xc.z - a0.z) + fabsf(xc.w - a0.w);
            float v = warp_sum(diff) * 0.5f;        // halves duplicated -> exact /2
            if (lane == 0) S.scorev[n] = v;
        }
    }
    if (tid >= NPG) S.scorev[tid] = -3.4e38f;
    __syncthreads();

    // ====== Phase 2: hybrid bitonic sort on packed u64 (score desc, idx asc)
    unsigned long long key;
    {
        float sc = S.scorev[tid];
        unsigned sb  = __float_as_uint(sc);
        unsigned ord = (sb & 0x80000000u) ? ~sb : (sb | 0x80000000u);
        key = ((unsigned long long)ord << 32) | (unsigned)(~tid);
    }
    unsigned long long* kb64 = reinterpret_cast<unsigned long long*>(S.arena);

    #pragma unroll
    for (int k = 2; k <= 32; k <<= 1) {         // k = 2..32 in registers
        #pragma unroll
        for (int j = k >> 1; j > 0; j >>= 1) {
            unsigned long long pk = shfl_xor_u64(key, j);
            bool isLow   = ((lane & j) == 0);
            bool dirDesc = ((tid  & k) == 0);
            bool takeMax = (isLow == dirDesc);
            key = ((pk > key) == takeMax) ? pk : key;
        }
    }
    #pragma unroll
    for (int k = 64; k <= NTH; k <<= 1) {       // k = 64..512
        for (int j = k >> 1; j >= 32; j >>= 1) {
            kb64[tid] = key;
            __syncthreads();
            unsigned long long pk = kb64[tid ^ j];
            bool isLow   = ((tid & j) == 0);
            bool dirDesc = ((tid & k) == 0);
            bool takeMax = (isLow == dirDesc);
            key = ((pk > key) == takeMax) ? pk : key;
            __syncthreads();
        }
        #pragma unroll
        for (int j = 16; j > 0; j >>= 1) {
            unsigned long long pk = shfl_xor_u64(key, j);
            bool isLow   = ((lane & j) == 0);
            bool dirDesc = ((tid  & k) == 0);
            bool takeMax = (isLow == dirDesc);
            key = ((pk > key) == takeMax) ? pk : key;
        }
    }
    for (int n = tid; n < NPG; n += NTH) S.mapv[n] = -1;
    __syncthreads();
    if (tid < KPG) {
        int idx = (int)(~(unsigned)key) & (NTH - 1);
        S.klist[tid] = (unsigned short)idx;
        S.mapv[idx]  = (short)tid;
    }
    __syncthreads();

    // ====== Phase 3a: W1/b1 stage, in-place CSR compaction, d2 ==============
    {
        const float4* src = reinterpret_cast<const float4*>(W1);
        float4*       dst = reinterpret_cast<float4*>(&S.u2.mm.W1s[0][0]);
        for (int i = tid; i < F_ * F_ / 4; i += NTH) dst[i] = src[i];
    }
    if (tid < F_) S.u2.mm.b1s[tid] = b1[tid];
    const float beta = beta_p[0];

    if (tid < KPG) {
        int n = S.klist[tid];
        unsigned kb = n ? S.col_off[n - 1] : 0u;
        unsigned ke = S.col_off[n];
        unsigned w  = kb;
        for (unsigned k = kb; k < ke; ++k) {
            short m = S.mapv[S.csr_src[k]];
            if (m >= 0) S.csr_src[w++] = (unsigned short)m;
        }
        int cnt = (int)(w - kb);
        S.vcnt[tid] = (unsigned short)cnt;
        S.d2k[tid]  = 1.0f / sqrtf((float)(cnt + 1));
    }
    __syncthreads();

    // ====== Phase 3b: z-gather (global) + matmul + fused 4a epilogue ========
    float2* HB2 = reinterpret_cast<float2*>(S.arena);
    const float2* W2 = reinterpret_cast<const float2*>(&S.u2.mm.W1s[0][0]);
    {
        float2 b2 = reinterpret_cast<const float2*>(S.u2.mm.b1s)[lane];
        for (int i0 = 2 * wid; i0 < KPG; i0 += 2 * NW) {
            #pragma unroll
            for (int r = 0; r < 2; ++r) {
                int i = i0 + r;
                if (i >= KPG) break;
                int n = S.klist[i];
                float d2c = S.d2k[i];
                const float2* xr = reinterpret_cast<const float2*>(xg + (size_t)n * F_);
                float2 xv = xr[lane];
                float  sf = d2c * d2c;
                float2 z  = make_float2(sf * xv.x, sf * xv.y);
                unsigned kb = n ? S.col_off[n - 1] : 0u;
                unsigned ke = kb + S.vcnt[i];
                for (unsigned k = kb; k < ke; ++k) {
                    int rs = S.csr_src[k];
                    float nm = S.d2k[rs] * d2c;
                    const float2* xj = reinterpret_cast<const float2*>(
                        xg + (size_t)S.klist[rs] * F_);
                    float2 xw = xj[lane];
                    z.x = fmaf(nm, xw.x, z.x);
                    z.y = fmaf(nm, xw.y, z.y);
                }
                reinterpret_cast<float2*>(S.u2.mm.zst[wid][r])[lane] = z;
            }
            __syncwarp();
            const float2* Z0 = reinterpret_cast<const float2*>(S.u2.mm.zst[wid][0]);
            const float2* Z1 = reinterpret_cast<const float2*>(S.u2.mm.zst[wid][1]);
            float2 a0 = b2, a1 = b2;
            #pragma unroll
            for (int kk = 0; kk < F_ / 2; ++kk) {
                float2 zp0 = Z0[kk];
                float2 zp1 = Z1[kk];
                float2 wA  = W2[(2 * kk)     * 32 + lane];
                float2 wB  = W2[(2 * kk + 1) * 32 + lane];
                a0.x = fmaf(zp0.x, wA.x, a0.x);  a0.y = fmaf(zp0.x, wA.y, a0.y);
                a0.x = fmaf(zp0.y, wB.x, a0.x);  a0.y = fmaf(zp0.y, wB.y, a0.y);
                a1.x = fmaf(zp1.x, wA.x, a1.x);  a1.y = fmaf(zp1.x, wA.y, a1.y);
                a1.x = fmaf(zp1.y, wB.x, a1.x);  a1.y = fmaf(zp1.y, wB.y, a1.y);
            }
            a0.x = fmaxf(a0.x, 0.f);  a0.y = fmaxf(a0.y, 0.f);
            a1.x = fmaxf(a1.x, 0.f);  a1.y = fmaxf(a1.y, 0.f);
            HB2[i0 * 32 + lane] = a0;
            {
                float ss = warp_sum(a0.x * a0.x + a0.y * a0.y);
                float ni = 1.0f / fmaxf(sqrtf(ss), 1e-12f);
                if (lane == 0) {
                    S.ninv[i0]   = ni;
                    S.scorev[i0] = beta * ss * ni * ni;
                }
            }
            if (i0 + 1 < KPG) {
                HB2[(i0 + 1) * 32 + lane] = a1;
                float ss = warp_sum(a1.x * a1.x + a1.y * a1.y);
                float ni = 1.0f / fmaxf(sqrtf(ss), 1e-12f);
                if (lane == 0) {
                    S.ninv[i0 + 1]   = ni;
                    S.scorev[i0 + 1] = beta * ss * ni * ni;
                }
            }
            __syncwarp();
        }
    }
    __syncthreads();

    // ====== Phase 4: AGNN chunk-4 online softmax + fused readout ============
    float2 msum = make_float2(0.f, 0.f);
    float2 mmax = make_float2(-3.4e38f, -3.4e38f);
    for (int i = wid; i < KPG; i += NW) {
        int n = S.klist[i];
        unsigned kb = n ? S.col_off[n - 1] : 0u;
        int dv = (int)S.vcnt[i];
        float ni = S.ninv[i];
        float2 hn = HB2[i * 32 + lane];
        float m     = S.scorev[i];                  // logit_s
        float denom = 1.0f;
        float2 acc  = hn;
        for (int c = 0; c < dv; c += 4) {
            int cnt = dv - c;  if (cnt > 4) cnt = 4;
            int   rs0, rs1, rs2, rs3;
            float d0, d1, d2, d3;
            rs0 = S.csr_src[kb + c];
            rs1 = (cnt > 1) ? (int)S.csr_src[kb + c + 1] : rs0;
            rs2 = (cnt > 2) ? (int)S.csr_src[kb + c + 2] : rs0;
            rs3 = (cnt > 3) ? (int)S.csr_src[kb + c + 3] : rs0;
            {
                float2 h0 = HB2[rs0 * 32 + lane];
                float2 h1 = HB2[rs1 * 32 + lane];
                float2 h2 = HB2[rs2 * 32 + lane];
                float2 h3 = HB2[rs3 * 32 + lane];
                d0 = fmaf(hn.x, h0.x, hn.y * h0.y);
                d1 = fmaf(hn.x, h1.x, hn.y * h1.y);
                d2 = fmaf(hn.x, h2.x, hn.y * h2.y);
                d3 = fmaf(hn.x, h3.x, hn.y * h3.y);
            }
            #pragma unroll
            for (int o = 16; o; o >>= 1) {          // 4 interleaved trees
                d0 += __shfl_xor_sync(0xffffffffu, d0, o);
                d1 += __shfl_xor_sync(0xffffffffu, d1, o);
                d2 += __shfl_xor_sync(0xffffffffu, d2, o);
                d3 += __shfl_xor_sync(0xffffffffu, d3, o);
            }
            d0 = beta * d0 * ni * S.ninv[rs0];
            d1 = (cnt > 1) ? beta * d1 * ni * S.ninv[rs1] : -3.4e38f;
            d2 = (cnt > 2) ? beta * d2 * ni * S.ninv[rs2] : -3.4e38f;
            d3 = (cnt > 3) ? beta * d3 * ni * S.ninv[rs3] : -3.4e38f;
            float cm = fmaxf(fmaxf(d0, d1), fmaxf(d2, d3));
            float mn = fmaxf(m, cm);
            float cr = __expf(m - mn);
            denom *= cr;
            acc.x *= cr;  acc.y *= cr;
            {
                float e0 = __expf(d0 - mn);
                float2 hs = HB2[rs0 * 32 + lane];
                denom += e0;
                acc.x = fmaf(e0, hs.x, acc.x);
                acc.y = fmaf(e0, hs.y, acc.y);
            }
            if (cnt > 1) {
                float e1 = __expf(d1 - mn);
                float2 hs = HB2[rs1 * 32 + lane];
                denom += e1;
                acc.x = fmaf(e1, hs.x, acc.x);
                acc.y = fmaf(e1, hs.y, acc.y);
            }
            if (cnt > 2) {
                float e2 = __expf(d2 - mn);
                float2 hs = HB2[rs2 * 32 + lane];
                denom += e2;
                acc.x = fmaf(e2, hs.x, acc.x);
                acc.y = fmaf(e2, hs.y, acc.y);
            }
            if (cnt > 3) {
                float e3 = __expf(d3 - mn);
                float2 hs = HB2[rs3 * 32 + lane];
                denom += e3;
                acc.x = fmaf(e3, hs.x, acc.x);
                acc.y = fmaf(e3, hs.y, acc.y);
            }
            m = mn;
        }
        float inv = 1.0f / denom;
        float2 o = make_float2(acc.x * inv, acc.y * inv);
        msum.x += o.x;  msum.y += o.y;
        mmax.x = fmaxf(mmax.x, o.x);
        mmax.y = fmaxf(mmax.y, o.y);
    }
    __syncthreads();                                 // csr_src now dead
    {
        float* RS = reinterpret_cast<float*>(S.csr_src);        // [16][64]
        float* RM = RS + NW * F_;                               // [16][64]
        reinterpret_cast<float2*>(RS)[wid * 32 + lane] = msum;
        reinterpret_cast<float2*>(RM)[wid * 32 + lane] = mmax;
        __syncthreads();
        if (tid < F_) {
            float s = 0.f;
            #pragma unroll
            for (int w = 0; w < NW; ++w) s += RS[w * F_ + tid];
            out[(size_t)g * (2 * F_) + tid] = fmaxf(s * (1.0f / (float)KPG), 0.f);
        } else if (tid < 2 * F_) {
            int f = tid - F_;
            float m2 = -3.4e38f;
            #pragma unroll
            for (int w = 0; w < NW; ++w) m2 = fmaxf(m2, RM[w * F_ + f]);
            out[(size_t)g * (2 * F_) + F_ + f] = fmaxf(m2, 0.f);
        }
    }
}

extern "C" void kernel_launch(void* const* d_in, const int* in_sizes, int n_in,
                              void* d_out, int out_size)
{
    const float* x    = (const float*)d_in[0];
    const int*   ei   = (const int*)  d_in[1];
    const float* W1   = (const float*)d_in[2];
    const float* b1   = (const float*)d_in[3];
    const float* beta = (const float*)d_in[4];
    float*       out  = (float*)d_out;

    int smem = (int)sizeof(SmemLayout);
    cudaFuncSetAttribute(gp_fused_kernel,
                         cudaFuncAttributeMaxDynamicSharedMemorySize, smem);
    gp_fused_kernel<<<G_, NTH, smem>>>(x, ei, W1, b1, beta, out);
}

// round 15
// speedup vs baseline: 1.0692x; 1.0170x over previous
#include <cuda_runtime.h>
#include <cstdint>

#define G_   200
#define NPG  500
#define EPG  6000
#define ETOT (G_*EPG)
#define F_   64
#define KPG  250
#define NTH  512
#define NW   (NTH/32)

struct __align__(16) SmemLayout {
    float           arena[NPG * 32];            // u64 sort buf(P2) / HB(P3+)
    union {                                     // 24832B
        struct {
            float W1s[F_][F_];                  // 16384B (P3+)
            float b1s[F_];
            float zst[NW][2][F_];               // 8192B
        } mm;
        unsigned pe[EPG];                       // packed (r<<16|c) edges (P0)
    } u2;
    unsigned short  csr_src[EPG];               // 12000B; overlaid by rsum/rmax at readout
    unsigned        col_off[NPG + 4];
    float           dis[NPG];
    float           scorev[NTH];                // icnt(P0) -> scores(P1) -> logit_s(P3b+)
    int             sidx[NTH];                  // outdeg(P0)
    int             wsum[32];
    unsigned short  klist[KPG + 2];
    short           mapv[NPG];
    float           d2k[KPG];
    float           ninv[KPG];
    unsigned short  vcnt[KPG + 2];
};

__device__ __forceinline__ float warp_sum(float v) {
    #pragma unroll
    for (int o = 16; o; o >>= 1) v += __shfl_xor_sync(0xffffffffu, v, o);
    return v;
}
__device__ __forceinline__ unsigned long long shfl_xor_u64(unsigned long long v, int m) {
    unsigned lo = (unsigned)v, hi = (unsigned)(v >> 32);
    lo = __shfl_xor_sync(0xffffffffu, lo, m);
    hi = __shfl_xor_sync(0xffffffffu, hi, m);
    return ((unsigned long long)hi << 32) | lo;
}

__global__ __launch_bounds__(NTH, 2)
void gp_fused_kernel(const float* __restrict__ x,
                     const int*   __restrict__ ei,
                     const float* __restrict__ W1,
                     const float* __restrict__ b1,
                     const float* __restrict__ beta_p,
                     float*       __restrict__ out)
{
    extern __shared__ __align__(16) unsigned char smraw[];
    SmemLayout& S = *reinterpret_cast<SmemLayout*>(smraw);

    const int g    = blockIdx.x;
    const int tid  = threadIdx.x;
    const int wid  = tid >> 5;
    const int lane = tid & 31;
    const int hw   = lane >> 4;                 // half-warp id
    const int hl   = lane & 15;                 // lane in half
    const int base = g * NPG;
    const int* __restrict__ erow = ei + (size_t)g * EPG;
    const int* __restrict__ ecol = ei + (size_t)ETOT + (size_t)g * EPG;
    const float* __restrict__ xg = x + (size_t)base * F_;

    // ===== Phase 0: degrees + packed-edge cache + CSR ========================
    int* icnt = reinterpret_cast<int*>(S.scorev);
    icnt[tid]   = 0;
    S.sidx[tid] = 0;
    __syncthreads();

    for (int e = tid; e < EPG; e += NTH) {          // single global edge sweep
        int r = erow[e] - base;
        int c = ecol[e] - base;
        S.u2.pe[e] = ((unsigned)r << 16) | (unsigned)c;
        atomicAdd(&S.sidx[r], 1);
        atomicAdd(&icnt[c],  1);
    }
    __syncthreads();

    for (int n = tid; n < NPG; n += NTH) {
        int d = S.sidx[n];
        S.dis[n] = (d > 0) ? (1.0f / sqrtf((float)d)) : 0.0f;
    }
    {   // hierarchical exclusive scan of icnt -> col_off starts
        int v = icnt[tid];
        int inc = v;
        #pragma unroll
        for (int o = 1; o < 32; o <<= 1) {
            int u = __shfl_up_sync(0xffffffffu, inc, o);
            if (lane >= o) inc += u;
        }
        if (lane == 31) S.wsum[wid] = inc;
        __syncthreads();
        if (tid < 16) {
            int s = S.wsum[tid];
            #pragma unroll
            for (int o = 1; o < 16; o <<= 1) {
                int u = __shfl_up_sync(0x0000ffffu, s, o);
                if (tid >= o) s += u;
            }
            S.wsum[tid] = s;
        }
        __syncthreads();
        int pre = (wid > 0) ? S.wsum[wid - 1] : 0;
        if (tid < NPG + 1) S.col_off[tid] = (unsigned)(inc - v + pre);
    }
    __syncthreads();

    for (int e = tid; e < EPG; e += NTH) {          // scatter from SMEM cache
        unsigned p = S.u2.pe[e];
        int r = (int)(p >> 16);
        int c = (int)(p & 0xffffu);
        unsigned pos = atomicAdd(&S.col_off[c], 1u);
        S.csr_src[pos] = (unsigned short)r;
    }
    __syncthreads();
    // segment(n) = [ n? col_off[n-1]:0 , col_off[n] )

    // ===== Phase 1: score — half-warp float4 edges (2 edges/warp-iter) ======
    for (int n = wid; n < NPG; n += NW) {
        float4 xc = reinterpret_cast<const float4*>(xg + (size_t)n * F_)[hl];
        float  dn = S.dis[n];
        unsigned kb = n ? S.col_off[n - 1] : 0u;
        unsigned ke = S.col_off[n];
        float4 a0 = make_float4(0.f, 0.f, 0.f, 0.f);
        float4 a1 = make_float4(0.f, 0.f, 0.f, 0.f);
        unsigned k = kb + (unsigned)hw;
        for (; k + 2 < ke; k += 4) {            // 2 edges for this half
            int s0 = S.csr_src[k];
            int s1 = S.csr_src[k + 2];
            float4 v0 = reinterpret_cast<const float4*>(xg + (size_t)s0 * F_)[hl];
            float4 v1 = reinterpret_cast<const float4*>(xg + (size_t)s1 * F_)[hl];
            float w0 = S.dis[s0] * dn;
            float w1 = S.dis[s1] * dn;
            a0.x = fmaf(w0, v0.x, a0.x);  a0.y = fmaf(w0, v0.y, a0.y);
            a0.z = fmaf(w0, v0.z, a0.z);  a0.w = fmaf(w0, v0.w, a0.w);
            a1.x = fmaf(w1, v1.x, a1.x);  a1.y = fmaf(w1, v1.y, a1.y);
            a1.z = fmaf(w1, v1.z, a1.z);  a1.w = fmaf(w1, v1.w, a1.w);
        }
        for (; k < ke; k += 2) {                // remainder edge
            int s = S.csr_src[k];
            float4 v = reinterpret_cast<const float4*>(xg + (size_t)s * F_)[hl];
            float w = S.dis[s] * dn;
            a0.x = fmaf(w, v.x, a0.x);  a0.y = fmaf(w, v.y, a0.y);
            a0.z = fmaf(w, v.z, a0.z);  a0.w = fmaf(w, v.w, a0.w);
        }
        a0.x += a1.x;  a0.y += a1.y;  a0.z += a1.z;  a0.w += a1.w;
        a0.x += __shfl_xor_sync(0xffffffffu, a0.x, 16);
        a0.y += __shfl_xor_sync(0xffffffffu, a0.y, 16);
        a0.z += __shfl_xor_sync(0xffffffffu, a0.z, 16);
        a0.w += __shfl_xor_sync(0xffffffffu, a0.w, 16);
        float diff = fabsf(xc.x - a0.x) + fabsf(xc.y - a0.y)
                   + fabsf(xc.z - a0.z) + fabsf(xc.w - a0.w);
        float v = warp_sum(diff) * 0.5f;        // halves duplicated -> exact /2
        if (lane == 0) S.scorev[n] = v;
    }
    if (tid >= NPG) S.scorev[tid] = -3.4e38f;
    __syncthreads();

    // ====== Phase 2: hybrid bitonic sort on packed u64 (score desc, idx asc)
    unsigned long long key;
    {
        float sc = S.scorev[tid];
        unsigned sb  = __float_as_uint(sc);
        unsigned ord = (sb & 0x80000000u) ? ~sb : (sb | 0x80000000u);
        key = ((unsigned long long)ord << 32) | (unsigned)(~tid);
    }
    unsigned long long* kb64 = reinterpret_cast<unsigned long long*>(S.arena);

    #pragma unroll
    for (int k = 2; k <= 32; k <<= 1) {         // k = 2..32 in registers
        #pragma unroll
        for (int j = k >> 1; j > 0; j >>= 1) {
            unsigned long long pk = shfl_xor_u64(key, j);
            bool isLow   = ((lane & j) == 0);
            bool dirDesc = ((tid  & k) == 0);
            bool takeMax = (isLow == dirDesc);
            key = ((pk > key) == takeMax) ? pk : key;
        }
    }
    #pragma unroll
    for (int k = 64; k <= NTH; k <<= 1) {       // k = 64..512
        for (int j = k >> 1; j >= 32; j >>= 1) {
            kb64[tid] = key;
            __syncthreads();
            unsigned long long pk = kb64[tid ^ j];
            bool isLow   = ((tid & j) == 0);
            bool dirDesc = ((tid & k) == 0);
            bool takeMax = (isLow == dirDesc);
            key = ((pk > key) == takeMax) ? pk : key;
            __syncthreads();
        }
        #pragma unroll
        for (int j = 16; j > 0; j >>= 1) {
            unsigned long long pk = shfl_xor_u64(key, j);
            bool isLow   = ((lane & j) == 0);
            bool dirDesc = ((tid  & k) == 0);
            bool takeMax = (isLow == dirDesc);
            key = ((pk > key) == takeMax) ? pk : key;
        }
    }
    for (int n = tid; n < NPG; n += NTH) S.mapv[n] = -1;
    __syncthreads();
    if (tid < KPG) {
        int idx = (int)(~(unsigned)key) & (NTH - 1);
        S.klist[tid] = (unsigned short)idx;
        S.mapv[idx]  = (short)tid;
    }
    __syncthreads();

    // ====== Phase 3a: W1/b1 stage, in-place CSR compaction, d2 ==============
    {
        const float4* src = reinterpret_cast<const float4*>(W1);
        float4*       dst = reinterpret_cast<float4*>(&S.u2.mm.W1s[0][0]);
        for (int i = tid; i < F_ * F_ / 4; i += NTH) dst[i] = src[i];
    }
    if (tid < F_) S.u2.mm.b1s[tid] = b1[tid];
    const float beta = beta_p[0];

    if (tid < KPG) {
        int n = S.klist[tid];
        unsigned kb = n ? S.col_off[n - 1] : 0u;
        unsigned ke = S.col_off[n];
        unsigned w  = kb;
        for (unsigned k = kb; k < ke; ++k) {
            short m = S.mapv[S.csr_src[k]];
            if (m >= 0) S.csr_src[w++] = (unsigned short)m;
        }
        int cnt = (int)(w - kb);
        S.vcnt[tid] = (unsigned short)cnt;
        S.d2k[tid]  = 1.0f / sqrtf((float)(cnt + 1));
    }
    __syncthreads();

    // ====== Phase 3b: half-warp z-gather + matmul + fused 4a epilogue =======
    float2* HB2 = reinterpret_cast<float2*>(S.arena);
    const float2* W2 = reinterpret_cast<const float2*>(&S.u2.mm.W1s[0][0]);
    {
        float2 b2 = reinterpret_cast<const float2*>(S.u2.mm.b1s)[lane];
        for (int i0 = 2 * wid; i0 < KPG; i0 += 2 * NW) {
            // gather: half 0 -> row i0, half 1 -> row i0+1 (float4 lanes)
            {
                bool act = (hw == 0) || (i0 + 1 < KPG);
                int  i   = act ? (i0 + hw) : i0;
                int  n   = S.klist[i];
                float dd = S.d2k[i];
                float4 xv = reinterpret_cast<const float4*>(xg + (size_t)n * F_)[hl];
                float sf = dd * dd;
                float4 z = make_float4(sf * xv.x, sf * xv.y, sf * xv.z, sf * xv.w);
                unsigned kb = n ? S.col_off[n - 1] : 0u;
                int cnt   = act ? (int)S.vcnt[i] : 0;
                int cnt_o = __shfl_xor_sync(0xffffffffu, cnt, 16);
                int kmax  = cnt > cnt_o ? cnt : cnt_o;
                for (int k = 0; k < kmax; ++k) {
                    bool v = k < cnt;
                    int rs = v ? (int)S.csr_src[kb + k] : 0;
                    float nm = v ? S.d2k[rs] * dd : 0.f;
                    float4 xw = reinterpret_cast<const float4*>(
                        xg + (size_t)S.klist[rs] * F_)[hl];
                    z.x = fmaf(nm, xw.x, z.x);  z.y = fmaf(nm, xw.y, z.y);
                    z.z = fmaf(nm, xw.z, z.z);  z.w = fmaf(nm, xw.w, z.w);
                }
                reinterpret_cast<float4*>(S.u2.mm.zst[wid][hw])[hl] = z;
            }
            __syncwarp();
            const float2* Z0 = reinterpret_cast<const float2*>(S.u2.mm.zst[wid][0]);
            const float2* Z1 = reinterpret_cast<const float2*>(S.u2.mm.zst[wid][1]);
            float2 a0 = b2, a1 = b2;
            #pragma unroll
            for (int kk = 0; kk < F_ / 2; ++kk) {
                float2 zp0 = Z0[kk];
                float2 zp1 = Z1[kk];
                float2 wA  = W2[(2 * kk)     * 32 + lane];
                float2 wB  = W2[(2 * kk + 1) * 32 + lane];
                a0.x = fmaf(zp0.x, wA.x, a0.x);  a0.y = fmaf(zp0.x, wA.y, a0.y);
                a0.x = fmaf(zp0.y, wB.x, a0.x);  a0.y = fmaf(zp0.y, wB.y, a0.y);
                a1.x = fmaf(zp1.x, wA.x, a1.x);  a1.y = fmaf(zp1.x, wA.y, a1.y);
                a1.x = fmaf(zp1.y, wB.x, a1.x);  a1.y = fmaf(zp1.y, wB.y, a1.y);
            }
            a0.x = fmaxf(a0.x, 0.f);  a0.y = fmaxf(a0.y, 0.f);
            a1.x = fmaxf(a1.x, 0.f);  a1.y = fmaxf(a1.y, 0.f);
            HB2[i0 * 32 + lane] = a0;
            {
                float ss = warp_sum(a0.x * a0.x + a0.y * a0.y);
                float ni = 1.0f / fmaxf(sqrtf(ss), 1e-12f);
                if (lane == 0) {
                    S.ninv[i0]   = ni;
                    S.scorev[i0] = beta * ss * ni * ni;
                }
            }
            if (i0 + 1 < KPG) {
                HB2[(i0 + 1) * 32 + lane] = a1;
                float ss = warp_sum(a1.x * a1.x + a1.y * a1.y);
                float ni = 1.0f / fmaxf(sqrtf(ss), 1e-12f);
                if (lane == 0) {
                    S.ninv[i0 + 1]   = ni;
                    S.scorev[i0 + 1] = beta * ss * ni * ni;
                }
            }
            __syncwarp();
        }
    }
    __syncthreads();

    // ====== Phase 4: half-warp split online softmax + fused readout =========
    const float4* HB4 = reinterpret_cast<const float4*>(S.arena);
    float4 msum = make_float4(0.f, 0.f, 0.f, 0.f);
    float4 mmax = make_float4(-3.4e38f, -3.4e38f, -3.4e38f, -3.4e38f);
    for (int i = wid; i < KPG; i += NW) {
        int n = S.klist[i];
        unsigned kb = n ? S.col_off[n - 1] : 0u;
        int dv = (int)S.vcnt[i];
        float ni = S.ninv[i];
        float4 hn = HB4[i * 16 + hl];
        float ls = S.scorev[i];
        float m    = hw ? -3.4e38f : ls;
        float den  = hw ? 0.f : 1.f;
        float4 acc = hw ? make_float4(0.f, 0.f, 0.f, 0.f) : hn;
        for (int c = 0; c < dv; c += 4) {
            int e0 = c + hw, e1 = c + 2 + hw;
            bool v0 = e0 < dv, v1 = e1 < dv;
            int rs0 = v0 ? (int)S.csr_src[kb + e0] : (int)S.csr_src[kb];
            int rs1 = v1 ? (int)S.csr_src[kb + e1] : rs0;
            float4 ha = HB4[rs0 * 16 + hl];
            float4 hb = HB4[rs1 * 16 + hl];
            float d0 = fmaf(hn.x, ha.x, fmaf(hn.y, ha.y, fmaf(hn.z, ha.z, hn.w * ha.w)));
            float d1 = fmaf(hn.x, hb.x, fmaf(hn.y, hb.y, fmaf(hn.z, hb.z, hn.w * hb.w)));
            #pragma unroll
            for (int o = 8; o; o >>= 1) {       // 16-lane butterflies, 2 interleaved
                d0 += __shfl_xor_sync(0xffffffffu, d0, o);
                d1 += __shfl_xor_sync(0xffffffffu, d1, o);
            }
            d0 = v0 ? beta * d0 * ni * S.ninv[rs0] : -3.4e38f;
            d1 = v1 ? beta * d1 * ni * S.ninv[rs1] : -3.4e38f;
            float mn = fmaxf(m, fmaxf(d0, d1));
            float cr = __expf(m - mn);
            float e0x = v0 ? __expf(d0 - mn) : 0.f;
            float e1x = v1 ? __expf(d1 - mn) : 0.f;
            den  = den * cr + e0x + e1x;
            acc.x = fmaf(acc.x, cr, fmaf(e0x, ha.x, e1x * hb.x));
            acc.y = fmaf(acc.y, cr, fmaf(e0x, ha.y, e1x * hb.y));
            acc.z = fmaf(acc.z, cr, fmaf(e0x, ha.z, e1x * hb.z));
            acc.w = fmaf(acc.w, cr, fmaf(e0x, ha.w, e1x * hb.w));
            m = mn;
        }
        // merge the two half-softmaxes (exact)
        float mo = __shfl_xor_sync(0xffffffffu, m, 16);
        float mn = fmaxf(m, mo);
        float cr = __expf(m - mn);
        den *= cr;
        acc.x *= cr;  acc.y *= cr;  acc.z *= cr;  acc.w *= cr;
        den   += __shfl_xor_sync(0xffffffffu, den, 16);
        acc.x += __shfl_xor_sync(0xffffffffu, acc.x, 16);
        acc.y += __shfl_xor_sync(0xffffffffu, acc.y, 16);
        acc.z += __shfl_xor_sync(0xffffffffu, acc.z, 16);
        acc.w += __shfl_xor_sync(0xffffffffu, acc.w, 16);
        float inv = 1.0f / den;
        float4 o4 = make_float4(acc.x * inv, acc.y * inv, acc.z * inv, acc.w * inv);
        msum.x += o4.x;  msum.y += o4.y;  msum.z += o4.z;  msum.w += o4.w;
        mmax.x = fmaxf(mmax.x, o4.x);  mmax.y = fmaxf(mmax.y, o4.y);
        mmax.z = fmaxf(mmax.z, o4.z);  mmax.w = fmaxf(mmax.w, o4.w);
    }
    __syncthreads();                                 // csr_src now dead
    {
        float* RS = reinterpret_cast<float*>(S.csr_src);        // [16][64]
        float* RM = RS + NW * F_;                               // [16][64]
        if (hw == 0) {                                          // halves duplicated
            reinterpret_cast<float4*>(RS)[wid * 16 + hl] = msum;
            reinterpret_cast<float4*>(RM)[wid * 16 + hl] = mmax;
        }
        __syncthreads();
        if (tid < F_) {
            float s = 0.f;
            #pragma unroll
            for (int w = 0; w < NW; ++w) s += RS[w * F_ + tid];
            out[(size_t)g * (2 * F_) + tid] = fmaxf(s * (1.0f / (float)KPG), 0.f);
        } else if (tid < 2 * F_) {
            int f = tid - F_;
            float m2 = -3.4e38f;
            #pragma unroll
            for (int w = 0; w < NW; ++w) m2 = fmaxf(m2, RM[w * F_ + f]);
            out[(size_t)g * (2 * F_) + F_ + f] = fmaxf(m2, 0.f);
        }
    }
}

extern "C" void kernel_launch(void* const* d_in, const int* in_sizes, int n_in,
                              void* d_out, int out_size)
{
    const float* x    = (const float*)d_in[0];
    const int*   ei   = (const int*)  d_in[1];
    const float* W1   = (const float*)d_in[2];
    const float* b1   = (const float*)d_in[3];
    const float* beta = (const float*)d_in[4];
    float*       out  = (float*)d_out;

    int smem = (int)sizeof(SmemLayout);
    cudaFuncSetAttribute(gp_fused_kernel,
                         cudaFuncAttributeMaxDynamicSharedMemorySize, smem);
    gp_fused_kernel<<<G_, NTH, smem>>>(x, ei, W1, b1, beta, out);
}

// round 16
// speedup vs baseline: 1.0880x; 1.0175x over previous
#include <cuda_runtime.h>
#include <cstdint>

#define G_   200
#define NPG  500
#define EPG  6000
#define ETOT (G_*EPG)
#define F_   64
#define KPG  250
#define NTH  512
#define NW   (NTH/32)

struct __align__(16) SmemLayout {
    float           arena[NPG * 32];            // u64 sort buf(P2) / HB(P3+)
    union {                                     // 24832B
        struct {
            float W1s[F_][F_];                  // 16384B (P3+)
            float b1s[F_];
            float zst[NW][2][F_];               // 8192B
        } mm;
        unsigned pe[EPG];                       // packed (r<<16|c) edges (P0)
    } u2;
    unsigned short  csr_src[EPG];               // 12000B; overlaid by rsum/rmax at readout
    unsigned        col_off[NPG + 4];
    float           dis[NPG];
    float           scorev[NTH];                // icnt(P0) -> scores(P1) -> logit_s(P3b+)
    int             sidx[NTH];                  // outdeg(P0)
    int             wsum[32];
    unsigned short  klist[KPG + 2];
    short           mapv[NPG];
    float           d2k[KPG];
    float           ninv[KPG];
    unsigned short  vcnt[KPG + 2];
};

__device__ __forceinline__ float warp_sum(float v) {
    #pragma unroll
    for (int o = 16; o; o >>= 1) v += __shfl_xor_sync(0xffffffffu, v, o);
    return v;
}
__device__ __forceinline__ unsigned long long shfl_xor_u64(unsigned long long v, int m) {
    unsigned lo = (unsigned)v, hi = (unsigned)(v >> 32);
    lo = __shfl_xor_sync(0xffffffffu, lo, m);
    hi = __shfl_xor_sync(0xffffffffu, hi, m);
    return ((unsigned long long)hi << 32) | lo;
}

__global__ __launch_bounds__(NTH, 2)
void gp_fused_kernel(const float* __restrict__ x,
                     const int*   __restrict__ ei,
                     const float* __restrict__ W1,
                     const float* __restrict__ b1,
                     const float* __restrict__ beta_p,
                     float*       __restrict__ out)
{
    extern __shared__ __align__(16) unsigned char smraw[];
    SmemLayout& S = *reinterpret_cast<SmemLayout*>(smraw);

    const int g    = blockIdx.x;
    const int tid  = threadIdx.x;
    const int wid  = tid >> 5;
    const int lane = tid & 31;
    const int hw   = lane >> 4;                 // half-warp id
    const int hl   = lane & 15;                 // lane in half
    const int base = g * NPG;
    const int* __restrict__ erow = ei + (size_t)g * EPG;
    const int* __restrict__ ecol = ei + (size_t)ETOT + (size_t)g * EPG;
    const float* __restrict__ xg = x + (size_t)base * F_;

    // ===== Phase 0: degrees + packed-edge cache + CSR (int4 sweeps) =========
    int* icnt = reinterpret_cast<int*>(S.scorev);
    icnt[tid]   = 0;
    S.sidx[tid] = 0;
    __syncthreads();

    {
        const int4* er4 = reinterpret_cast<const int4*>(erow);
        const int4* ec4 = reinterpret_cast<const int4*>(ecol);
        uint4* pe4 = reinterpret_cast<uint4*>(S.u2.pe);
        for (int e4 = tid; e4 < EPG / 4; e4 += NTH) {
            int4 r4 = er4[e4];
            int4 c4 = ec4[e4];
            r4.x -= base; r4.y -= base; r4.z -= base; r4.w -= base;
            c4.x -= base; c4.y -= base; c4.z -= base; c4.w -= base;
            uint4 p;
            p.x = ((unsigned)r4.x << 16) | (unsigned)c4.x;
            p.y = ((unsigned)r4.y << 16) | (unsigned)c4.y;
            p.z = ((unsigned)r4.z << 16) | (unsigned)c4.z;
            p.w = ((unsigned)r4.w << 16) | (unsigned)c4.w;
            pe4[e4] = p;
            atomicAdd(&S.sidx[r4.x], 1);  atomicAdd(&icnt[c4.x], 1);
            atomicAdd(&S.sidx[r4.y], 1);  atomicAdd(&icnt[c4.y], 1);
            atomicAdd(&S.sidx[r4.z], 1);  atomicAdd(&icnt[c4.z], 1);
            atomicAdd(&S.sidx[r4.w], 1);  atomicAdd(&icnt[c4.w], 1);
        }
    }
    __syncthreads();

    for (int n = tid; n < NPG; n += NTH) {
        int d = S.sidx[n];
        S.dis[n] = (d > 0) ? (1.0f / sqrtf((float)d)) : 0.0f;
    }
    {   // hierarchical exclusive scan of icnt -> col_off starts
        int v = icnt[tid];
        int inc = v;
        #pragma unroll
        for (int o = 1; o < 32; o <<= 1) {
            int u = __shfl_up_sync(0xffffffffu, inc, o);
            if (lane >= o) inc += u;
        }
        if (lane == 31) S.wsum[wid] = inc;
        __syncthreads();
        if (tid < 16) {
            int s = S.wsum[tid];
            #pragma unroll
            for (int o = 1; o < 16; o <<= 1) {
                int u = __shfl_up_sync(0x0000ffffu, s, o);
                if (tid >= o) s += u;
            }
            S.wsum[tid] = s;
        }
        __syncthreads();
        int pre = (wid > 0) ? S.wsum[wid - 1] : 0;
        if (tid < NPG + 1) S.col_off[tid] = (unsigned)(inc - v + pre);
    }
    __syncthreads();

    {   // scatter from SMEM cache (uint4 reads)
        const uint4* pe4 = reinterpret_cast<const uint4*>(S.u2.pe);
        for (int e4 = tid; e4 < EPG / 4; e4 += NTH) {
            uint4 p = pe4[e4];
            unsigned q;
            q = atomicAdd(&S.col_off[p.x & 0xffffu], 1u);
            S.csr_src[q] = (unsigned short)(p.x >> 16);
            q = atomicAdd(&S.col_off[p.y & 0xffffu], 1u);
            S.csr_src[q] = (unsigned short)(p.y >> 16);
            q = atomicAdd(&S.col_off[p.z & 0xffffu], 1u);
            S.csr_src[q] = (unsigned short)(p.z >> 16);
            q = atomicAdd(&S.col_off[p.w & 0xffffu], 1u);
            S.csr_src[q] = (unsigned short)(p.w >> 16);
        }
    }
    __syncthreads();
    // segment(n) = [ n? col_off[n-1]:0 , col_off[n] )

    // ===== Phase 1: score — half-warp float4 edges (2 edges/warp-iter) ======
    for (int n = wid; n < NPG; n += NW) {
        float4 xc = reinterpret_cast<const float4*>(xg + (size_t)n * F_)[hl];
        float  dn = S.dis[n];
        unsigned kb = n ? S.col_off[n - 1] : 0u;
        unsigned ke = S.col_off[n];
        float4 a0 = make_float4(0.f, 0.f, 0.f, 0.f);
        float4 a1 = make_float4(0.f, 0.f, 0.f, 0.f);
        unsigned k = kb + (unsigned)hw;
        for (; k + 2 < ke; k += 4) {            // 2 edges for this half
            int s0 = S.csr_src[k];
            int s1 = S.csr_src[k + 2];
            float4 v0 = reinterpret_cast<const float4*>(xg + (size_t)s0 * F_)[hl];
            float4 v1 = reinterpret_cast<const float4*>(xg + (size_t)s1 * F_)[hl];
            float w0 = S.dis[s0] * dn;
            float w1 = S.dis[s1] * dn;
            a0.x = fmaf(w0, v0.x, a0.x);  a0.y = fmaf(w0, v0.y, a0.y);
            a0.z = fmaf(w0, v0.z, a0.z);  a0.w = fmaf(w0, v0.w, a0.w);
            a1.x = fmaf(w1, v1.x, a1.x);  a1.y = fmaf(w1, v1.y, a1.y);
            a1.z = fmaf(w1, v1.z, a1.z);  a1.w = fmaf(w1, v1.w, a1.w);
        }
        for (; k < ke; k += 2) {                // remainder edge
            int s = S.csr_src[k];
            float4 v = reinterpret_cast<const float4*>(xg + (size_t)s * F_)[hl];
            float w = S.dis[s] * dn;
            a0.x = fmaf(w, v.x, a0.x);  a0.y = fmaf(w, v.y, a0.y);
            a0.z = fmaf(w, v.z, a0.z);  a0.w = fmaf(w, v.w, a0.w);
        }
        a0.x += a1.x;  a0.y += a1.y;  a0.z += a1.z;  a0.w += a1.w;
        a0.x += __shfl_xor_sync(0xffffffffu, a0.x, 16);
        a0.y += __shfl_xor_sync(0xffffffffu, a0.y, 16);
        a0.z += __shfl_xor_sync(0xffffffffu, a0.z, 16);
        a0.w += __shfl_xor_sync(0xffffffffu, a0.w, 16);
        float diff = fabsf(xc.x - a0.x) + fabsf(xc.y - a0.y)
                   + fabsf(xc.z - a0.z) + fabsf(xc.w - a0.w);
        float v = warp_sum(diff) * 0.5f;        // halves duplicated -> exact /2
        if (lane == 0) S.scorev[n] = v;
    }
    if (tid >= NPG) S.scorev[tid] = -3.4e38f;
    __syncthreads();

    // ====== Phase 2: hybrid bitonic sort on packed u64 (score desc, idx asc)
    unsigned long long key;
    {
        float sc = S.scorev[tid];
        unsigned sb  = __float_as_uint(sc);
        unsigned ord = (sb & 0x80000000u) ? ~sb : (sb | 0x80000000u);
        key = ((unsigned long long)ord << 32) | (unsigned)(~tid);
    }
    unsigned long long* kb64 = reinterpret_cast<unsigned long long*>(S.arena);

    #pragma unroll
    for (int k = 2; k <= 32; k <<= 1) {         // k = 2..32 in registers
        #pragma unroll
        for (int j = k >> 1; j > 0; j >>= 1) {
            unsigned long long pk = shfl_xor_u64(key, j);
            bool isLow   = ((lane & j) == 0);
            bool dirDesc = ((tid  & k) == 0);
            bool takeMax = (isLow == dirDesc);
            key = ((pk > key) == takeMax) ? pk : key;
        }
    }
    #pragma unroll
    for (int k = 64; k <= NTH; k <<= 1) {       // k = 64..512
        for (int j = k >> 1; j >= 32; j >>= 1) {
            kb64[tid] = key;
            __syncthreads();
            unsigned long long pk = kb64[tid ^ j];
            bool isLow   = ((tid & j) == 0);
            bool dirDesc = ((tid & k) == 0);
            bool takeMax = (isLow == dirDesc);
            key = ((pk > key) == takeMax) ? pk : key;
            __syncthreads();
        }
        #pragma unroll
        for (int j = 16; j > 0; j >>= 1) {
            unsigned long long pk = shfl_xor_u64(key, j);
            bool isLow   = ((lane & j) == 0);
            bool dirDesc = ((tid  & k) == 0);
            bool takeMax = (isLow == dirDesc);
            key = ((pk > key) == takeMax) ? pk : key;
        }
    }
    for (int n = tid; n < NPG; n += NTH) S.mapv[n] = -1;
    __syncthreads();
    if (tid < KPG) {
        int idx = (int)(~(unsigned)key) & (NTH - 1);
        S.klist[tid] = (unsigned short)idx;
        S.mapv[idx]  = (short)tid;
    }
    __syncthreads();

    // ====== Phase 3a: W1/b1 stage, in-place CSR compaction, d2 ==============
    {
        const float4* src = reinterpret_cast<const float4*>(W1);
        float4*       dst = reinterpret_cast<float4*>(&S.u2.mm.W1s[0][0]);
        for (int i = tid; i < F_ * F_ / 4; i += NTH) dst[i] = src[i];
    }
    if (tid < F_) S.u2.mm.b1s[tid] = b1[tid];
    const float beta = beta_p[0];

    if (tid < KPG) {
        int n = S.klist[tid];
        unsigned kb = n ? S.col_off[n - 1] : 0u;
        unsigned ke = S.col_off[n];
        unsigned w  = kb;
        for (unsigned k = kb; k < ke; ++k) {
            short m = S.mapv[S.csr_src[k]];
            if (m >= 0) S.csr_src[w++] = (unsigned short)m;
        }
        int cnt = (int)(w - kb);
        S.vcnt[tid] = (unsigned short)cnt;
        S.d2k[tid]  = 1.0f / sqrtf((float)(cnt + 1));
    }
    __syncthreads();

    // ====== Phase 3b: half-warp z-gather + matmul + fused 4a epilogue =======
    float2* HB2 = reinterpret_cast<float2*>(S.arena);
    const float2* W2 = reinterpret_cast<const float2*>(&S.u2.mm.W1s[0][0]);
    {
        float2 b2 = reinterpret_cast<const float2*>(S.u2.mm.b1s)[lane];
        for (int i0 = 2 * wid; i0 < KPG; i0 += 2 * NW) {
            // gather: half 0 -> row i0, half 1 -> row i0+1 (float4 lanes)
            {
                bool act = (hw == 0) || (i0 + 1 < KPG);
                int  i   = act ? (i0 + hw) : i0;
                int  n   = S.klist[i];
                float dd = S.d2k[i];
                float4 xv = reinterpret_cast<const float4*>(xg + (size_t)n * F_)[hl];
                float sf = dd * dd;
                float4 z = make_float4(sf * xv.x, sf * xv.y, sf * xv.z, sf * xv.w);
                unsigned kb = n ? S.col_off[n - 1] : 0u;
                int cnt   = act ? (int)S.vcnt[i] : 0;
                int cnt_o = __shfl_xor_sync(0xffffffffu, cnt, 16);
                int kmax  = cnt > cnt_o ? cnt : cnt_o;
                for (int k = 0; k < kmax; ++k) {
                    bool v = k < cnt;
                    int rs = v ? (int)S.csr_src[kb + k] : 0;
                    float nm = v ? S.d2k[rs] * dd : 0.f;
                    float4 xw = reinterpret_cast<const float4*>(
                        xg + (size_t)S.klist[rs] * F_)[hl];
                    z.x = fmaf(nm, xw.x, z.x);  z.y = fmaf(nm, xw.y, z.y);
                    z.z = fmaf(nm, xw.z, z.z);  z.w = fmaf(nm, xw.w, z.w);
                }
                reinterpret_cast<float4*>(S.u2.mm.zst[wid][hw])[hl] = z;
            }
            __syncwarp();
            const float2* Z0 = reinterpret_cast<const float2*>(S.u2.mm.zst[wid][0]);
            const float2* Z1 = reinterpret_cast<const float2*>(S.u2.mm.zst[wid][1]);
            float2 a0 = b2, a1 = b2;
            #pragma unroll
            for (int kk = 0; kk < F_ / 2; ++kk) {
                float2 zp0 = Z0[kk];
                float2 zp1 = Z1[kk];
                float2 wA  = W2[(2 * kk)     * 32 + lane];
                float2 wB  = W2[(2 * kk + 1) * 32 + lane];
                a0.x = fmaf(zp0.x, wA.x, a0.x);  a0.y = fmaf(zp0.x, wA.y, a0.y);
                a0.x = fmaf(zp0.y, wB.x, a0.x);  a0.y = fmaf(zp0.y, wB.y, a0.y);
                a1.x = fmaf(zp1.x, wA.x, a1.x);  a1.y = fmaf(zp1.x, wA.y, a1.y);
                a1.x = fmaf(zp1.y, wB.x, a1.x);  a1.y = fmaf(zp1.y, wB.y, a1.y);
            }
            a0.x = fmaxf(a0.x, 0.f);  a0.y = fmaxf(a0.y, 0.f);
            a1.x = fmaxf(a1.x, 0.f);  a1.y = fmaxf(a1.y, 0.f);
            HB2[i0 * 32 + lane] = a0;
            {
                float ss = warp_sum(a0.x * a0.x + a0.y * a0.y);
                float ni = 1.0f / fmaxf(sqrtf(ss), 1e-12f);
                if (lane == 0) {
                    S.ninv[i0]   = ni;
                    S.scorev[i0] = beta * ss * ni * ni;
                }
            }
            if (i0 + 1 < KPG) {
                HB2[(i0 + 1) * 32 + lane] = a1;
                float ss = warp_sum(a1.x * a1.x + a1.y * a1.y);
                float ni = 1.0f / fmaxf(sqrtf(ss), 1e-12f);
                if (lane == 0) {
                    S.ninv[i0 + 1]   = ni;
                    S.scorev[i0 + 1] = beta * ss * ni * ni;
                }
            }
            __syncwarp();
        }
    }
    __syncthreads();

    // ====== Phase 4: half-warp split online softmax + fused readout =========
    const float4* HB4 = reinterpret_cast<const float4*>(S.arena);
    float4 msum = make_float4(0.f, 0.f, 0.f, 0.f);
    float4 mmax = make_float4(-3.4e38f, -3.4e38f, -3.4e38f, -3.4e38f);
    for (int i = wid; i < KPG; i += NW) {
        int n = S.klist[i];
        unsigned kb = n ? S.col_off[n - 1] : 0u;
        int dv = (int)S.vcnt[i];
        float ni = S.ninv[i];
        float4 hn = HB4[i * 16 + hl];
        float ls = S.scorev[i];
        float m    = hw ? -3.4e38f : ls;
        float den  = hw ? 0.f : 1.f;
        float4 acc = hw ? make_float4(0.f, 0.f, 0.f, 0.f) : hn;
        for (int c = 0; c < dv; c += 4) {
            int e0 = c + hw, e1 = c + 2 + hw;
            bool v0 = e0 < dv, v1 = e1 < dv;
            int rs0 = v0 ? (int)S.csr_src[kb + e0] : 0;
            int rs1 = v1 ? (int)S.csr_src[kb + e1] : 0;
            float4 ha = HB4[rs0 * 16 + hl];
            float4 hb = HB4[rs1 * 16 + hl];
            float d0 = fmaf(hn.x, ha.x, fmaf(hn.y, ha.y, fmaf(hn.z, ha.z, hn.w * ha.w)));
            float d1 = fmaf(hn.x, hb.x, fmaf(hn.y, hb.y, fmaf(hn.z, hb.z, hn.w * hb.w)));
            #pragma unroll
            for (int o = 8; o; o >>= 1) {       // 16-lane butterflies, 2 interleaved
                d0 += __shfl_xor_sync(0xffffffffu, d0, o);
                d1 += __shfl_xor_sync(0xffffffffu, d1, o);
            }
            d0 = v0 ? beta * d0 * ni * S.ninv[rs0] : -3.4e38f;
            d1 = v1 ? beta * d1 * ni * S.ninv[rs1] : -3.4e38f;
            float mn = fmaxf(m, fmaxf(d0, d1));
            float cr = __expf(m - mn);
            float e0x = v0 ? __expf(d0 - mn) : 0.f;
            float e1x = v1 ? __expf(d1 - mn) : 0.f;
            den  = den * cr + e0x + e1x;
            acc.x = fmaf(acc.x, cr, fmaf(e0x, ha.x, e1x * hb.x));
            acc.y = fmaf(acc.y, cr, fmaf(e0x, ha.y, e1x * hb.y));
            acc.z = fmaf(acc.z, cr, fmaf(e0x, ha.z, e1x * hb.z));
            acc.w = fmaf(acc.w, cr, fmaf(e0x, ha.w, e1x * hb.w));
            m = mn;
        }
        // merge the two half-softmaxes (exact)
        float mo = __shfl_xor_sync(0xffffffffu, m, 16);
        float mn = fmaxf(m, mo);
        float cr = __expf(m - mn);
        den *= cr;
        acc.x *= cr;  acc.y *= cr;  acc.z *= cr;  acc.w *= cr;
        den   += __shfl_xor_sync(0xffffffffu, den, 16);
        acc.x += __shfl_xor_sync(0xffffffffu, acc.x, 16);
        acc.y += __shfl_xor_sync(0xffffffffu, acc.y, 16);
        acc.z += __shfl_xor_sync(0xffffffffu, acc.z, 16);
        acc.w += __shfl_xor_sync(0xffffffffu, acc.w, 16);
        float inv = 1.0f / den;
        float4 o4 = make_float4(acc.x * inv, acc.y * inv, acc.z * inv, acc.w * inv);
        msum.x += o4.x;  msum.y += o4.y;  msum.z += o4.z;  msum.w += o4.w;
        mmax.x = fmaxf(mmax.x, o4.x);  mmax.y = fmaxf(mmax.y, o4.y);
        mmax.z = fmaxf(mmax.z, o4.z);  mmax.w = fmaxf(mmax.w, o4.w);
    }
    __syncthreads();                                 // csr_src now dead
    {
        float* RS = reinterpret_cast<float*>(S.csr_src);        // [16][64]
        float* RM = RS + NW * F_;                               // [16][64]
        if (hw == 0) {                                          // halves duplicated
            reinterpret_cast<float4*>(RS)[wid * 16 + hl] = msum;
            reinterpret_cast<float4*>(RM)[wid * 16 + hl] = mmax;
        }
        __syncthreads();
        if (tid < F_) {
            float s = 0.f;
            #pragma unroll
            for (int w = 0; w < NW; ++w) s += RS[w * F_ + tid];
            out[(size_t)g * (2 * F_) + tid] = fmaxf(s * (1.0f / (float)KPG), 0.f);
        } else if (tid < 2 * F_) {
            int f = tid - F_;
            float m2 = -3.4e38f;
            #pragma unroll
            for (int w = 0; w < NW; ++w) m2 = fmaxf(m2, RM[w * F_ + f]);
            out[(size_t)g * (2 * F_) + F_ + f] = fmaxf(m2, 0.f);
        }
    }
}

extern "C" void kernel_launch(void* const* d_in, const int* in_sizes, int n_in,
                              void* d_out, int out_size)
{
    const float* x    = (const float*)d_in[0];
    const int*   ei   = (const int*)  d_in[1];
    const float* W1   = (const float*)d_in[2];
    const float* b1   = (const float*)d_in[3];
    const float* beta = (const float*)d_in[4];
    float*       out  = (float*)d_out;

    int smem = (int)sizeof(SmemLayout);
    cudaFuncSetAttribute(gp_fused_kernel,
                         cudaFuncAttributeMaxDynamicSharedMemorySize, smem);
    gp_fused_kernel<<<G_, NTH, smem>>>(x, ei, W1, b1, beta, out);
}

// round 17
// speedup vs baseline: 1.1392x; 1.0471x over previous
#include <cuda_runtime.h>
#include <cstdint>

#define G_   200
#define NPG  500
#define EPG  6000
#define ETOT (G_*EPG)
#define F_   64
#define KPG  250
#define NTH  512
#define NW   (NTH/32)

struct __align__(16) SmemLayout {
    float           arena[NPG * 32];            // radix hist(P2) / HB(P3+)
    union {                                     // 24832B
        struct {
            float W1s[F_][F_];                  // 16384B (P3+)
            float b1s[F_];
            float zst[NW][2][F_];               // 8192B
        } mm;
        unsigned pe[EPG];                       // packed (r<<16|c) edges (P0)
    } u2;
    unsigned short  csr_src[EPG];               // 12000B; overlaid by rsum/rmax at readout
    unsigned        col_off[NPG + 4];
    float           dis[NPG];
    float           scorev[NTH];                // icnt(P0) -> scores(P1) -> logit_s(P3b+)
    int             sidx[NTH];                  // outdeg(P0)
    int             wsum[32];
    unsigned short  klist[KPG + 2];
    short           mapv[NPG];
    float           d2k[KPG];
    float           ninv[KPG];
    unsigned short  vcnt[KPG + 2];
};

__device__ __forceinline__ float warp_sum(float v) {
    #pragma unroll
    for (int o = 16; o; o >>= 1) v += __shfl_xor_sync(0xffffffffu, v, o);
    return v;
}

__global__ __launch_bounds__(NTH, 2)
void gp_fused_kernel(const float* __restrict__ x,
                     const int*   __restrict__ ei,
                     const float* __restrict__ W1,
                     const float* __restrict__ b1,
                     const float* __restrict__ beta_p,
                     float*       __restrict__ out)
{
    extern __shared__ __align__(16) unsigned char smraw[];
    SmemLayout& S = *reinterpret_cast<SmemLayout*>(smraw);

    const int g    = blockIdx.x;
    const int tid  = threadIdx.x;
    const int wid  = tid >> 5;
    const int lane = tid & 31;
    const int hw   = lane >> 4;                 // half-warp id
    const int hl   = lane & 15;                 // lane in half
    const int base = g * NPG;
    const int* __restrict__ erow = ei + (size_t)g * EPG;
    const int* __restrict__ ecol = ei + (size_t)ETOT + (size_t)g * EPG;
    const float* __restrict__ xg = x + (size_t)base * F_;

    // ===== Phase 0: degrees + packed-edge cache + CSR (int4 sweeps) =========
    int* icnt = reinterpret_cast<int*>(S.scorev);
    icnt[tid]   = 0;
    S.sidx[tid] = 0;
    __syncthreads();

    {
        const int4* er4 = reinterpret_cast<const int4*>(erow);
        const int4* ec4 = reinterpret_cast<const int4*>(ecol);
        uint4* pe4 = reinterpret_cast<uint4*>(S.u2.pe);
        for (int e4 = tid; e4 < EPG / 4; e4 += NTH) {
            int4 r4 = er4[e4];
            int4 c4 = ec4[e4];
            r4.x -= base; r4.y -= base; r4.z -= base; r4.w -= base;
            c4.x -= base; c4.y -= base; c4.z -= base; c4.w -= base;
            uint4 p;
            p.x = ((unsigned)r4.x << 16) | (unsigned)c4.x;
            p.y = ((unsigned)r4.y << 16) | (unsigned)c4.y;
            p.z = ((unsigned)r4.z << 16) | (unsigned)c4.z;
            p.w = ((unsigned)r4.w << 16) | (unsigned)c4.w;
            pe4[e4] = p;
            atomicAdd(&S.sidx[r4.x], 1);  atomicAdd(&icnt[c4.x], 1);
            atomicAdd(&S.sidx[r4.y], 1);  atomicAdd(&icnt[c4.y], 1);
            atomicAdd(&S.sidx[r4.z], 1);  atomicAdd(&icnt[c4.z], 1);
            atomicAdd(&S.sidx[r4.w], 1);  atomicAdd(&icnt[c4.w], 1);
        }
    }
    __syncthreads();

    for (int n = tid; n < NPG; n += NTH) {
        int d = S.sidx[n];
        S.dis[n] = (d > 0) ? (1.0f / sqrtf((float)d)) : 0.0f;
    }
    {   // hierarchical exclusive scan of icnt -> col_off starts
        int v = icnt[tid];
        int inc = v;
        #pragma unroll
        for (int o = 1; o < 32; o <<= 1) {
            int u = __shfl_up_sync(0xffffffffu, inc, o);
            if (lane >= o) inc += u;
        }
        if (lane == 31) S.wsum[wid] = inc;
        __syncthreads();
        if (tid < 16) {
            int s = S.wsum[tid];
            #pragma unroll
            for (int o = 1; o < 16; o <<= 1) {
                int u = __shfl_up_sync(0x0000ffffu, s, o);
                if (tid >= o) s += u;
            }
            S.wsum[tid] = s;
        }
        __syncthreads();
        int pre = (wid > 0) ? S.wsum[wid - 1] : 0;
        if (tid < NPG + 1) S.col_off[tid] = (unsigned)(inc - v + pre);
    }
    __syncthreads();

    {   // scatter from SMEM cache (uint4 reads)
        const uint4* pe4 = reinterpret_cast<const uint4*>(S.u2.pe);
        for (int e4 = tid; e4 < EPG / 4; e4 += NTH) {
            uint4 p = pe4[e4];
            unsigned q;
            q = atomicAdd(&S.col_off[p.x & 0xffffu], 1u);
            S.csr_src[q] = (unsigned short)(p.x >> 16);
            q = atomicAdd(&S.col_off[p.y & 0xffffu], 1u);
            S.csr_src[q] = (unsigned short)(p.y >> 16);
            q = atomicAdd(&S.col_off[p.z & 0xffffu], 1u);
            S.csr_src[q] = (unsigned short)(p.z >> 16);
            q = atomicAdd(&S.col_off[p.w & 0xffffu], 1u);
            S.csr_src[q] = (unsigned short)(p.w >> 16);
        }
    }
    __syncthreads();
    // segment(n) = [ n? col_off[n-1]:0 , col_off[n] )

    // ===== Phase 1: score — half-warp float4 edges; dn folded out ===========
    for (int n = wid; n < NPG; n += NW) {
        float4 xc = reinterpret_cast<const float4*>(xg + (size_t)n * F_)[hl];
        float  dn = S.dis[n];
        unsigned kb = n ? S.col_off[n - 1] : 0u;
        unsigned ke = S.col_off[n];
        float4 a0 = make_float4(0.f, 0.f, 0.f, 0.f);
        float4 a1 = make_float4(0.f, 0.f, 0.f, 0.f);
        unsigned k = kb + (unsigned)hw;
        for (; k + 2 < ke; k += 4) {            // 2 edges for this half
            int s0 = S.csr_src[k];
            int s1 = S.csr_src[k + 2];
            float4 v0 = reinterpret_cast<const float4*>(xg + (size_t)s0 * F_)[hl];
            float4 v1 = reinterpret_cast<const float4*>(xg + (size_t)s1 * F_)[hl];
            float w0 = S.dis[s0];
            float w1 = S.dis[s1];
            a0.x = fmaf(w0, v0.x, a0.x);  a0.y = fmaf(w0, v0.y, a0.y);
            a0.z = fmaf(w0, v0.z, a0.z);  a0.w = fmaf(w0, v0.w, a0.w);
            a1.x = fmaf(w1, v1.x, a1.x);  a1.y = fmaf(w1, v1.y, a1.y);
            a1.z = fmaf(w1, v1.z, a1.z);  a1.w = fmaf(w1, v1.w, a1.w);
        }
        for (; k < ke; k += 2) {                // remainder edge
            int s = S.csr_src[k];
            float4 v = reinterpret_cast<const float4*>(xg + (size_t)s * F_)[hl];
            float w = S.dis[s];
            a0.x = fmaf(w, v.x, a0.x);  a0.y = fmaf(w, v.y, a0.y);
            a0.z = fmaf(w, v.z, a0.z);  a0.w = fmaf(w, v.w, a0.w);
        }
        a0.x += a1.x;  a0.y += a1.y;  a0.z += a1.z;  a0.w += a1.w;
        a0.x += __shfl_xor_sync(0xffffffffu, a0.x, 16);
        a0.y += __shfl_xor_sync(0xffffffffu, a0.y, 16);
        a0.z += __shfl_xor_sync(0xffffffffu, a0.z, 16);
        a0.w += __shfl_xor_sync(0xffffffffu, a0.w, 16);
        float diff = fabsf(xc.x - dn * a0.x) + fabsf(xc.y - dn * a0.y)
                   + fabsf(xc.z - dn * a0.z) + fabsf(xc.w - dn * a0.w);
        float v = warp_sum(diff) * 0.5f;        // halves duplicated -> exact /2
        if (lane == 0) S.scorev[n] = v;
    }
    __syncthreads();

    // ====== Phase 2: exact radix-select of top-KPG (score desc, idx asc) ====
    unsigned ord;
    {
        float sc = (tid < NPG) ? S.scorev[tid] : -3.4e38f;
        unsigned sb = __float_as_uint(sc);
        ord = (sb & 0x80000000u) ? ~sb : (sb | 0x80000000u);
    }
    int* hist = reinterpret_cast<int*>(S.arena);        // 256 bins
    int* bc   = hist + 256;                             // bc[0]=need bc[1]=prefix
    int need = KPG;
    unsigned prefix = 0;

    #pragma unroll
    for (int pass = 0; pass < 4; ++pass) {
        const int shift = 24 - 8 * pass;
        if (tid < 256) hist[tid] = 0;
        __syncthreads();
        bool act = (tid < NPG);
        if (pass > 0) act = act && ((ord >> (shift + 8)) == (prefix >> (shift + 8)));
        if (act) atomicAdd(&hist[(ord >> shift) & 255u], 1);
        __syncthreads();
        if (tid < 256) {                        // within-warp suffix sums
            int s = hist[tid];
            #pragma unroll
            for (int o = 1; o < 32; o <<= 1) {
                int u = __shfl_down_sync(0xffffffffu, s, o);
                if (lane + o < 32) s += u;
            }
            if (lane == 0) S.wsum[wid] = s;     // warp totals (wid 0..7)
            hist[tid] = s;                      // overwrite with warp-suffix
        }
        __syncthreads();
        if (tid < 256) {
            int s2 = hist[tid];
            int v  = (lane == 31) ? s2 : (s2 - hist[tid + 1]);
            int add = 0;
            for (int w = wid + 1; w < 8; ++w) add += S.wsum[w];
            int Sfx = s2 + add;                 // global suffix incl own bin
            if (Sfx >= need && (Sfx - v) < need) {
                bc[0] = need - (Sfx - v);
                bc[1] = (int)(prefix | ((unsigned)tid << shift));
            }
        }
        __syncthreads();
        need   = bc[0];
        prefix = (unsigned)bc[1];
        __syncthreads();
    }
    // prefix = exact threshold T; need = # to take among ord == T (idx asc)
    for (int n = tid; n < NPG; n += NTH) S.mapv[n] = -1;
    {
        int gt = (tid < NPG && ord > prefix) ? 1 : 0;
        int eq = (tid < NPG && ord == prefix) ? 1 : 0;
        int val = (gt << 10) | eq;
        int inc = val;
        #pragma unroll
        for (int o = 1; o < 32; o <<= 1) {
            int u = __shfl_up_sync(0xffffffffu, inc, o);
            if (lane >= o) inc += u;
        }
        if (lane == 31) S.wsum[wid] = inc;
        __syncthreads();
        if (tid < 16) {
            int s = S.wsum[tid];
            #pragma unroll
            for (int o = 1; o < 16; o <<= 1) {
                int u = __shfl_up_sync(0x0000ffffu, s, o);
                if (tid >= o) s += u;
            }
            S.wsum[tid] = s;
        }
        __syncthreads();
        int ex = inc - val + ((wid > 0) ? S.wsum[wid - 1] : 0);
        int exGT = ex >> 10, exEQ = ex & 1023;
        int totGT = KPG - need;
        int slot = -1;
        if (gt)                      slot = exGT;
        else if (eq && exEQ < need)  slot = totGT + exEQ;
        if (slot >= 0) {
            S.klist[slot] = (unsigned short)tid;
            S.mapv[tid]   = (short)slot;
        }
    }
    __syncthreads();

    // ====== Phase 3a: W1/b1 stage, in-place CSR compaction, d2 ==============
    {
        const float4* src = reinterpret_cast<const float4*>(W1);
        float4*       dst = reinterpret_cast<float4*>(&S.u2.mm.W1s[0][0]);
        for (int i = tid; i < F_ * F_ / 4; i += NTH) dst[i] = src[i];
    }
    if (tid < F_) S.u2.mm.b1s[tid] = b1[tid];
    const float beta = beta_p[0];

    if (tid < KPG) {
        int n = S.klist[tid];
        unsigned kb = n ? S.col_off[n - 1] : 0u;
        unsigned ke = S.col_off[n];
        unsigned w  = kb;
        for (unsigned k = kb; k < ke; ++k) {
            short m = S.mapv[S.csr_src[k]];
            if (m >= 0) S.csr_src[w++] = (unsigned short)m;
        }
        int cnt = (int)(w - kb);
        S.vcnt[tid] = (unsigned short)cnt;
        S.d2k[tid]  = 1.0f / sqrtf((float)(cnt + 1));
    }
    __syncthreads();

    // ====== Phase 3b: half-warp z-gather + matmul + fused 4a epilogue =======
    float2* HB2 = reinterpret_cast<float2*>(S.arena);
    const float2* W2 = reinterpret_cast<const float2*>(&S.u2.mm.W1s[0][0]);
    {
        float2 b2 = reinterpret_cast<const float2*>(S.u2.mm.b1s)[lane];
        for (int i0 = 2 * wid; i0 < KPG; i0 += 2 * NW) {
            // gather: half 0 -> row i0, half 1 -> row i0+1 (float4 lanes)
            {
                bool act = (hw == 0) || (i0 + 1 < KPG);
                int  i   = act ? (i0 + hw) : i0;
                int  n   = S.klist[i];
                float dd = S.d2k[i];
                float4 xv = reinterpret_cast<const float4*>(xg + (size_t)n * F_)[hl];
                float sf = dd * dd;
                float4 z = make_float4(sf * xv.x, sf * xv.y, sf * xv.z, sf * xv.w);
                unsigned kb = n ? S.col_off[n - 1] : 0u;
                int cnt   = act ? (int)S.vcnt[i] : 0;
                int cnt_o = __shfl_xor_sync(0xffffffffu, cnt, 16);
                int kmax  = cnt > cnt_o ? cnt : cnt_o;
                for (int k = 0; k < kmax; ++k) {
                    bool v = k < cnt;
                    int rs = v ? (int)S.csr_src[kb + k] : 0;
                    float nm = v ? S.d2k[rs] * dd : 0.f;
                    float4 xw = reinterpret_cast<const float4*>(
                        xg + (size_t)S.klist[rs] * F_)[hl];
                    z.x = fmaf(nm, xw.x, z.x);  z.y = fmaf(nm, xw.y, z.y);
                    z.z = fmaf(nm, xw.z, z.z);  z.w = fmaf(nm, xw.w, z.w);
                }
                reinterpret_cast<float4*>(S.u2.mm.zst[wid][hw])[hl] = z;
            }
            __syncwarp();
            const float2* Z0 = reinterpret_cast<const float2*>(S.u2.mm.zst[wid][0]);
            const float2* Z1 = reinterpret_cast<const float2*>(S.u2.mm.zst[wid][1]);
            float2 a0 = b2, a1 = b2;
            #pragma unroll
            for (int kk = 0; kk < F_ / 2; ++kk) {
                float2 zp0 = Z0[kk];
                float2 zp1 = Z1[kk];
                float2 wA  = W2[(2 * kk)     * 32 + lane];
                float2 wB  = W2[(2 * kk + 1) * 32 + lane];
                a0.x = fmaf(zp0.x, wA.x, a0.x);  a0.y = fmaf(zp0.x, wA.y, a0.y);
                a0.x = fmaf(zp0.y, wB.x, a0.x);  a0.y = fmaf(zp0.y, wB.y, a0.y);
                a1.x = fmaf(zp1.x, wA.x, a1.x);  a1.y = fmaf(zp1.x, wA.y, a1.y);
                a1.x = fmaf(zp1.y, wB.x, a1.x);  a1.y = fmaf(zp1.y, wB.y, a1.y);
            }
            a0.x = fmaxf(a0.x, 0.f);  a0.y = fmaxf(a0.y, 0.f);
            a1.x = fmaxf(a1.x, 0.f);  a1.y = fmaxf(a1.y, 0.f);
            HB2[i0 * 32 + lane] = a0;
            {
                float ss = warp_sum(a0.x * a0.x + a0.y * a0.y);
                float ni = 1.0f / fmaxf(sqrtf(ss), 1e-12f);
                if (lane == 0) {
                    S.ninv[i0]   = ni;
                    S.scorev[i0] = beta * ss * ni * ni;
                }
            }
            if (i0 + 1 < KPG) {
                HB2[(i0 + 1) * 32 + lane] = a1;
                float ss = warp_sum(a1.x * a1.x + a1.y * a1.y);
                float ni = 1.0f / fmaxf(sqrtf(ss), 1e-12f);
                if (lane == 0) {
                    S.ninv[i0 + 1]   = ni;
                    S.scorev[i0 + 1] = beta * ss * ni * ni;
                }
            }
            __syncwarp();
        }
    }
    __syncthreads();

    // ====== Phase 4: half-warp split online softmax + fused readout =========
    const float4* HB4 = reinterpret_cast<const float4*>(S.arena);
    float4 msum = make_float4(0.f, 0.f, 0.f, 0.f);
    float4 mmax = make_float4(-3.4e38f, -3.4e38f, -3.4e38f, -3.4e38f);
    for (int i = wid; i < KPG; i += NW) {
        int n = S.klist[i];
        unsigned kb = n ? S.col_off[n - 1] : 0u;
        int dv = (int)S.vcnt[i];
        float bni = beta * S.ninv[i];
        float4 hn = HB4[i * 16 + hl];
        float ls = S.scorev[i];
        float m    = hw ? -3.4e38f : ls;
        float den  = hw ? 0.f : 1.f;
        float4 acc = hw ? make_float4(0.f, 0.f, 0.f, 0.f) : hn;
        for (int c = 0; c < dv; c += 4) {
            int e0 = c + hw, e1 = c + 2 + hw;
            bool v0 = e0 < dv, v1 = e1 < dv;
            int rs0 = v0 ? (int)S.csr_src[kb + e0] : 0;
            int rs1 = v1 ? (int)S.csr_src[kb + e1] : 0;
            float4 ha = HB4[rs0 * 16 + hl];
            float4 hb = HB4[rs1 * 16 + hl];
            float d0 = fmaf(hn.x, ha.x, fmaf(hn.y, ha.y, fmaf(hn.z, ha.z, hn.w * ha.w)));
            float d1 = fmaf(hn.x, hb.x, fmaf(hn.y, hb.y, fmaf(hn.z, hb.z, hn.w * hb.w)));
            #pragma unroll
            for (int o = 8; o; o >>= 1) {       // 16-lane butterflies, 2 interleaved
                d0 += __shfl_xor_sync(0xffffffffu, d0, o);
                d1 += __shfl_xor_sync(0xffffffffu, d1, o);
            }
            d0 = v0 ? bni * d0 * S.ninv[rs0] : -3.4e38f;
            d1 = v1 ? bni * d1 * S.ninv[rs1] : -3.4e38f;
            float mn = fmaxf(m, fmaxf(d0, d1));
            float cr = __expf(m - mn);
            float e0x = v0 ? __expf(d0 - mn) : 0.f;
            float e1x = v1 ? __expf(d1 - mn) : 0.f;
            den  = den * cr + e0x + e1x;
            acc.x = fmaf(acc.x, cr, fmaf(e0x, ha.x, e1x * hb.x));
            acc.y = fmaf(acc.y, cr, fmaf(e0x, ha.y, e1x * hb.y));
            acc.z = fmaf(acc.z, cr, fmaf(e0x, ha.z, e1x * hb.z));
            acc.w = fmaf(acc.w, cr, fmaf(e0x, ha.w, e1x * hb.w));
            m = mn;
        }
        // merge the two half-softmaxes (exact)
        float mo = __shfl_xor_sync(0xffffffffu, m, 16);
        float mn = fmaxf(m, mo);
        float cr = __expf(m - mn);
        den *= cr;
        acc.x *= cr;  acc.y *= cr;  acc.z *= cr;  acc.w *= cr;
        den   += __shfl_xor_sync(0xffffffffu, den, 16);
        acc.x += __shfl_xor_sync(0xffffffffu, acc.x, 16);
        acc.y += __shfl_xor_sync(0xffffffffu, acc.y, 16);
        acc.z += __shfl_xor_sync(0xffffffffu, acc.z, 16);
        acc.w += __shfl_xor_sync(0xffffffffu, acc.w, 16);
        float inv = 1.0f / den;
        float4 o4 = make_float4(acc.x * inv, acc.y * inv, acc.z * inv, acc.w * inv);
        msum.x += o4.x;  msum.y += o4.y;  msum.z += o4.z;  msum.w += o4.w;
        mmax.x = fmaxf(mmax.x, o4.x);  mmax.y = fmaxf(mmax.y, o4.y);
        mmax.z = fmaxf(mmax.z, o4.z);  mmax.w = fmaxf(mmax.w, o4.w);
    }
    __syncthreads();                                 // csr_src now dead
    {
        float* RS = reinterpret_cast<float*>(S.csr_src);        // [16][64]
        float* RM = RS + NW * F_;                               // [16][64]
        if (hw == 0) {                                          // halves duplicated
            reinterpret_cast<float4*>(RS)[wid * 16 + hl] = msum;
            reinterpret_cast<float4*>(RM)[wid * 16 + hl] = mmax;
        }
        __syncthreads();
        if (tid < F_) {
            float s = 0.f;
            #pragma unroll
            for (int w = 0; w < NW; ++w) s += RS[w * F_ + tid];
            out[(size_t)g * (2 * F_) + tid] = fmaxf(s * (1.0f / (float)KPG), 0.f);
        } else if (tid < 2 * F_) {
            int f = tid - F_;
            float m2 = -3.4e38f;
            #pragma unroll
            for (int w = 0; w < NW; ++w) m2 = fmaxf(m2, RM[w * F_ + f]);
            out[(size_t)g * (2 * F_) + F_ + f] = fmaxf(m2, 0.f);
        }
    }
}

extern "C" void kernel_launch(void* const* d_in, const int* in_sizes, int n_in,
                              void* d_out, int out_size)
{
    const float* x    = (const float*)d_in[0];
    const int*   ei   = (const int*)  d_in[1];
    const float* W1   = (const float*)d_in[2];
    const float* b1   = (const float*)d_in[3];
    const float* beta = (const float*)d_in[4];
    float*       out  = (float*)d_out;

    int smem = (int)sizeof(SmemLayout);
    cudaFuncSetAttribute(gp_fused_kernel,
                         cudaFuncAttributeMaxDynamicSharedMemorySize, smem);
    gp_fused_kernel<<<G_, NTH, smem>>>(x, ei, W1, b1, beta, out);
}